// round 15
// baseline (speedup 1.0000x reference)
#include <cuda_runtime.h>
#include <cuda_bf16.h>
#include <cstdint>

#define BB 8
#define CC 256
#define HH_ 96
#define WW_ 96
#define NP_FULL 9216   // 96*96
#define GP 576         // 24*24
#define HGD 24
#define SCALE 0.17677669529663688f   // 32^-0.5

typedef unsigned long long ull;

__device__ __forceinline__ ull pack2(float x, float y) {
    ull r;
    asm("mov.b64 %0, {%1, %2};" : "=l"(r) : "f"(x), "f"(y));
    return r;
}
__device__ __forceinline__ void unpack2(ull v, float& x, float& y) {
    asm("mov.b64 {%0, %1}, %2;" : "=f"(x), "=f"(y) : "l"(v));
}
__device__ __forceinline__ ull fma2(ull a, ull b, ull c) {
    ull d;
    asm("fma.rn.f32x2 %0, %1, %2, %3;" : "=l"(d) : "l"(a), "l"(b), "l"(c));
    return d;
}
__device__ __forceinline__ uint32_t f2tf32(float x) {
    uint32_t r;
    asm("cvt.rna.tf32.f32 %0, %1;" : "=r"(r) : "f"(x));
    return r;
}
__device__ __forceinline__ void mma_tf32(float4& d,
    uint32_t a0, uint32_t a1, uint32_t a2, uint32_t a3,
    uint32_t b0, uint32_t b1) {
    asm volatile("mma.sync.aligned.m16n8k8.row.col.f32.tf32.tf32.f32 "
        "{%0,%1,%2,%3}, {%4,%5,%6,%7}, {%8,%9}, {%0,%1,%2,%3};"
        : "+f"(d.x), "+f"(d.y), "+f"(d.z), "+f"(d.w)
        : "r"(a0), "r"(a1), "r"(a2), "r"(a3), "r"(b0), "r"(b1));
}
__device__ __forceinline__ void cp16(uint32_t dst_smem, const float* src) {
    asm volatile("cp.async.cg.shared.global [%0], [%1], 16;"
                 :: "r"(dst_smem), "l"(src));
}
__device__ __forceinline__ void cp16z(uint32_t dst_smem, const float* src, int nbytes) {
    asm volatile("cp.async.cg.shared.global [%0], [%1], 16, %2;"
                 :: "r"(dst_smem), "l"(src), "r"(nbytes));
}

// ---------------- static scratch ----------------
__device__ float g_low[(size_t)BB*CC*GP];
__device__ float g_high[(size_t)BB*CC*NP_FULL];
__device__ float g_dw[(size_t)BB*CC*NP_FULL];
__device__ float g_dw2[(size_t)BB*CC*NP_FULL];
__device__ float g_lq[(size_t)BB*128*NP_FULL];
__device__ float g_lkvdw[(size_t)BB*CC*GP];
__device__ float g_lkv[(size_t)BB*CC*GP];
__device__ float g_lattn[(size_t)BB*128*NP_FULL];
__device__ float g_qkv[(size_t)BB*384*NP_FULL];
__device__ float g_ho[(size_t)BB*128*NP_FULL];

// ---------------- kernel 1: 4x4 avg pool ----------------
__global__ void pool_k(const float* __restrict__ x, float* __restrict__ low) {
    int i = blockIdx.x * blockDim.x + threadIdx.x;
    if (i >= BB*CC*GP) return;
    int g = i % GP; int bc = i / GP;
    int gy = g / HGD, gx = g % HGD;
    const float* xp = x + (size_t)bc*NP_FULL + (gy*4)*WW_ + gx*4;
    float s = 0.f;
#pragma unroll
    for (int r = 0; r < 4; r++) {
        float4 v = *(const float4*)(xp + r*WW_);
        s += (v.x + v.y) + (v.z + v.w);
    }
    low[i] = s * (1.0f/16.0f);
}

// ---------------- kernel 2: high = restore(pixelshuffle(low)) - x ----------------
// grid: (36 pixel-tiles, BB, 8 oc-chunks of 32)
__global__ void high_k(const float* __restrict__ x, const float* __restrict__ low,
                       const float* __restrict__ rw, const float* __restrict__ rb,
                       float* __restrict__ high) {
    __shared__ float ws[32*16];
    __shared__ float bs[32];
    int tid = threadIdx.x;
    int oc0 = blockIdx.z * 32;
    for (int i = tid; i < 32*16; i += 256) ws[i] = rw[oc0*16 + i];
    if (tid < 32) bs[tid] = rb[oc0 + tid];
    __syncthreads();
    int b = blockIdx.y;
    int p = blockIdx.x * 256 + tid;
    int h = p / WW_, w = p % WW_;
    int off = (h & 3)*4 + (w & 3);
    int g = (h >> 2)*HGD + (w >> 2);
    ull lv2[8];
#pragma unroll
    for (int ci = 0; ci < 8; ci++) {
        float a = low[((size_t)b*CC + (2*ci+0)*16 + off)*GP + g];
        float bb2 = low[((size_t)b*CC + (2*ci+1)*16 + off)*GP + g];
        lv2[ci] = pack2(a, bb2);
    }
    const float* xp = x + (size_t)b*CC*NP_FULL + (size_t)oc0*NP_FULL + p;
    float* hp = high + (size_t)b*CC*NP_FULL + (size_t)oc0*NP_FULL + p;
#pragma unroll 4
    for (int oc = 0; oc < 32; oc++) {
        const ull* wrow = (const ull*)&ws[oc*16];
        ull acc = 0ull;
#pragma unroll
        for (int ci = 0; ci < 8; ci++) acc = fma2(lv2[ci], wrow[ci], acc);
        float sx, sy; unpack2(acc, sx, sy);
        float s = bs[oc] + sx + sy;
        hp[(size_t)oc*NP_FULL] = s - xp[(size_t)oc*NP_FULL];
    }
}

// ---------------- kernel 3: depthwise 3x3 pad1, 8 cols x 4 rows per thread ----------------
// rolling input row: each of 6 input rows loaded once, fed to <=3 output accumulators.
__global__ void dw_k(const float* __restrict__ in, const float* __restrict__ w,
                     const float* __restrict__ bias, float* __restrict__ out,
                     int Ctot, int Hd, int Wd, int total32) {
    int i = blockIdx.x * blockDim.x + threadIdx.x;
    if (i >= total32) return;
    int w8 = Wd >> 3;
    int h4 = Hd >> 2;
    int xq = i % w8; int t = i / w8;
    int y4 = t % h4;
    int bcimg = t / h4;
    int c = bcimg % Ctot;
    int x0 = xq * 8;
    int y0 = y4 * 4;
    const float* ip = in + (size_t)bcimg * Hd * Wd;
    const float* wp = w + c*9;
    float wv[9];
#pragma unroll
    for (int k = 0; k < 9; k++) wv[k] = __ldg(wp + k);

    float bvv = bias[c];
    float a[4][8];
#pragma unroll
    for (int j2 = 0; j2 < 4; j2++)
#pragma unroll
        for (int j = 0; j < 8; j++) a[j2][j] = bvv;

#pragma unroll
    for (int rr = 0; rr < 6; rr++) {
        int yy = y0 + rr - 1;
        bool yok = (yy >= 0) && (yy < Hd);
        float r[10];
        if (yok) {
            const float* row = ip + yy*Wd;
            float4 m0 = *(const float4*)(row + x0);
            float4 m1 = *(const float4*)(row + x0 + 4);
            r[1] = m0.x; r[2] = m0.y; r[3] = m0.z; r[4] = m0.w;
            r[5] = m1.x; r[6] = m1.y; r[7] = m1.z; r[8] = m1.w;
            if (x0 > 0) {
                float4 L = *(const float4*)(row + x0 - 4);
                r[0] = L.w;
            } else r[0] = 0.f;
            if (x0 + 8 < Wd) {
                float4 R = *(const float4*)(row + x0 + 8);
                r[9] = R.x;
            } else r[9] = 0.f;
        } else {
#pragma unroll
            for (int j = 0; j < 10; j++) r[j] = 0.f;
        }
        // input row rr feeds output row j = rr - ky for ky in 0..2, 0 <= j < 4
#pragma unroll
        for (int ky = 0; ky < 3; ky++) {
            int j2 = rr - ky;
            if (j2 >= 0 && j2 < 4) {
#pragma unroll
                for (int dx = 0; dx < 3; dx++) {
                    float wc = wv[ky*3 + dx];
#pragma unroll
                    for (int j = 0; j < 8; j++)
                        a[j2][j] = fmaf(wc, r[j+dx], a[j2][j]);
                }
            }
        }
    }
    float* op = out + (size_t)bcimg*Hd*Wd + (size_t)y0*Wd + x0;
#pragma unroll
    for (int j2 = 0; j2 < 4; j2++) {
        float4 v0; v0.x=a[j2][0]; v0.y=a[j2][1]; v0.z=a[j2][2]; v0.w=a[j2][3];
        float4 v1; v1.x=a[j2][4]; v1.y=a[j2][5]; v1.z=a[j2][6]; v1.w=a[j2][7];
        *(float4*)(op + (size_t)j2*Wd)     = v0;
        *(float4*)(op + (size_t)j2*Wd + 4) = v1;
    }
}

// ---------------- pointwise 1x1 conv: tf32 MMA + 2-stage cp.async ----------------
#define AW 36
#define BW 136
#define ABUF (128*AW)
#define BBUF (32*BW)
#define PW_SMEM ((2*ABUF + 2*BBUF)*4)
__global__ __launch_bounds__(256, 2) void pw_mma_k(
    const float* __restrict__ in, const float* __restrict__ wgt,
    const float* __restrict__ bias, float* __restrict__ out,
    int IC, int NP, int out_cstride, int out_coff) {
    extern __shared__ float S[];
    float* Af = S;
    float* Bf = S + 2*ABUF;
    uint32_t sbase = (uint32_t)__cvta_generic_to_shared(S);
    int b = blockIdx.z;
    int oc0 = blockIdx.y * 128;
    int p0 = blockIdx.x * 128;
    int tid = threadIdx.x;
    int lane = tid & 31, wid = tid >> 5;
    int wm = wid >> 2, wn = wid & 3;
    int g = lane >> 2, tig = lane & 3;
    const float* inb = in + (size_t)b * IC * NP;

    float4 acc[4][4];
#pragma unroll
    for (int i = 0; i < 4; i++)
#pragma unroll
        for (int j = 0; j < 4; j++) acc[i][j] = make_float4(0.f, 0.f, 0.f, 0.f);

    int a_oc = tid >> 1;
    int a_kb = (tid & 1) * 16;
    int b_kk = tid >> 3;
    int b_pb = (tid & 7) * 16;

    int NIT = IC >> 5;
    bool full = (p0 + 128 <= NP);

    const float* wr0 = wgt + (size_t)(oc0 + a_oc)*IC + a_kb;
    const float* br0 = inb + (size_t)b_kk*NP + p0 + b_pb;
    uint32_t adst0 = sbase + (a_oc*AW + a_kb)*4;
    uint32_t bdst0 = sbase + (2*ABUF + b_kk*BW + b_pb)*4;

    auto stage = [&](int buf, int it) {
        const float* wr = wr0 + it*32;
        uint32_t adst = adst0 + buf*(ABUF*4);
#pragma unroll
        for (int q = 0; q < 4; q++)
            cp16(adst + q*16, wr + q*4);
        const float* brow = br0 + (size_t)it*32*NP;
        uint32_t bdst = bdst0 + buf*(BBUF*4);
        if (full) {
#pragma unroll
            for (int q = 0; q < 4; q++)
                cp16(bdst + q*16, brow + q*4);
        } else {
            int pg = p0 + b_pb;
#pragma unroll
            for (int q = 0; q < 4; q++) {
                int rem = (NP - (pg + q*4)) * 4;
                int nb = rem >= 16 ? 16 : (rem > 0 ? rem : 0);
                const float* src = brow + q*4;
                if (nb == 0) src = inb;
                cp16z(bdst + q*16, src, nb);
            }
        }
    };

    stage(0, 0);
    asm volatile("cp.async.commit_group;");

    for (int it = 0; it < NIT; it++) {
        int buf = it & 1;
        if (it + 1 < NIT) {
            stage(buf ^ 1, it + 1);
            asm volatile("cp.async.commit_group;");
            asm volatile("cp.async.wait_group 1;");
        } else {
            asm volatile("cp.async.wait_group 0;");
        }
        __syncthreads();
        const float* Ab = Af + buf*ABUF;
        const float* Bb = Bf + buf*BBUF;
#pragma unroll
        for (int ks = 0; ks < 32; ks += 8) {
            uint32_t af[4][4];
#pragma unroll
            for (int mt = 0; mt < 4; mt++) {
                int oc = wm*64 + mt*16 + g;
                af[mt][0] = f2tf32(Ab[(oc  )*AW + ks + tig]);
                af[mt][1] = f2tf32(Ab[(oc+8)*AW + ks + tig]);
                af[mt][2] = f2tf32(Ab[(oc  )*AW + ks + tig + 4]);
                af[mt][3] = f2tf32(Ab[(oc+8)*AW + ks + tig + 4]);
            }
            uint32_t bf[4][2];
#pragma unroll
            for (int nt = 0; nt < 4; nt++) {
                int p = wn*32 + nt*8 + g;
                bf[nt][0] = f2tf32(Bb[(ks+tig  )*BW + p]);
                bf[nt][1] = f2tf32(Bb[(ks+tig+4)*BW + p]);
            }
#pragma unroll
            for (int mt = 0; mt < 4; mt++)
#pragma unroll
                for (int nt = 0; nt < 4; nt++)
                    mma_tf32(acc[mt][nt], af[mt][0], af[mt][1], af[mt][2], af[mt][3],
                             bf[nt][0], bf[nt][1]);
        }
        __syncthreads();
    }
    float* ob = out + (size_t)b * out_cstride * NP + (size_t)out_coff * NP;
#pragma unroll
    for (int mt = 0; mt < 4; mt++) {
        int r0 = oc0 + wm*64 + mt*16 + g;
        int r1 = r0 + 8;
        float bv0 = __ldg(bias + r0);
        float bv1 = __ldg(bias + r1);
        float* row0 = ob + (size_t)r0 * NP;
        float* row1 = ob + (size_t)r1 * NP;
#pragma unroll
        for (int nt = 0; nt < 4; nt++) {
            int c = p0 + wn*32 + nt*8 + tig*2;
            float4 a = acc[mt][nt];
            if (c + 1 < NP) {
                float2 v0; v0.x = a.x + bv0; v0.y = a.y + bv0;
                float2 v1; v1.x = a.z + bv1; v1.y = a.w + bv1;
                *(float2*)(row0 + c) = v0;
                *(float2*)(row1 + c) = v1;
            } else if (c < NP) {
                row0[c] = a.x + bv0;
                row1[c] = a.z + bv1;
            }
        }
    }
}

// ---------------- low-frequency global attention: flash tf32 MMA ----------------
#define LSM_WORDS 50432
__global__ __launch_bounds__(256) void lattn_mma_k(
    const float* __restrict__ q, const float* __restrict__ kv,
    float* __restrict__ o) {
    extern __shared__ uint32_t Su[];
    uint32_t* Ps = Su;
    uint32_t* Ks = Su + 8704;
    uint32_t* Vs = Su + 27392;
    int b = blockIdx.z, h = blockIdx.y;
    int p0 = blockIdx.x * 128;
    int tid = threadIdx.x;
    int lane = tid & 31, w = tid >> 5;
    int g = lane >> 2, tig = lane & 3;
    const float* qb  = q  + ((size_t)b*128 + h*32)*NP_FULL;
    const float* kvb = kv + ((size_t)b*256 + h*32)*GP;

    for (int i = tid; i < 128*32; i += 256) {
        int d = i >> 7, pix = i & 127;
        Ps[pix*36 + d] = f2tf32(qb[(size_t)d*NP_FULL + p0 + pix] * SCALE);
    }
    for (int i = tid; i < 576*32; i += 256) {
        int d = i / 576, kp = i - d*576;
        Ks[d*584 + kp] = f2tf32(kvb[(size_t)d*GP + kp]);
    }
    for (int i = tid; i < 576*32; i += 256) {
        int d = i / 576, kp = i - d*576;
        Vs[kp*40 + d] = f2tf32(kvb[(size_t)(128 + d)*GP + kp]);
    }
    __syncthreads();

    int r0 = w*16 + g;
    uint32_t aq[4][4];
#pragma unroll
    for (int kt = 0; kt < 4; kt++) {
        aq[kt][0] = Ps[(r0  )*36 + kt*8 + tig];
        aq[kt][1] = Ps[(r0+8)*36 + kt*8 + tig];
        aq[kt][2] = Ps[(r0  )*36 + kt*8 + tig + 4];
        aq[kt][3] = Ps[(r0+8)*36 + kt*8 + tig + 4];
    }
    __syncwarp();

    float4 oacc[4];
#pragma unroll
    for (int dt = 0; dt < 4; dt++) oacc[dt] = make_float4(0.f,0.f,0.f,0.f);
    float m0 = -1e30f, m1 = -1e30f, l0 = 0.f, l1 = 0.f;

    for (int c = 0; c < 9; c++) {
        int kb = c*64;
        float4 s[8];
#pragma unroll
        for (int nt = 0; nt < 8; nt++) s[nt] = make_float4(0.f,0.f,0.f,0.f);
#pragma unroll
        for (int kt = 0; kt < 4; kt++) {
#pragma unroll
            for (int nt = 0; nt < 8; nt++) {
                uint32_t b0 = Ks[(kt*8+tig  )*584 + kb + nt*8 + g];
                uint32_t b1 = Ks[(kt*8+tig+4)*584 + kb + nt*8 + g];
                mma_tf32(s[nt], aq[kt][0], aq[kt][1], aq[kt][2], aq[kt][3], b0, b1);
            }
        }
        float mx0 = -1e30f, mx1 = -1e30f;
#pragma unroll
        for (int nt = 0; nt < 8; nt++) {
            mx0 = fmaxf(mx0, fmaxf(s[nt].x, s[nt].y));
            mx1 = fmaxf(mx1, fmaxf(s[nt].z, s[nt].w));
        }
        mx0 = fmaxf(mx0, __shfl_xor_sync(0xffffffffu, mx0, 1));
        mx0 = fmaxf(mx0, __shfl_xor_sync(0xffffffffu, mx0, 2));
        mx1 = fmaxf(mx1, __shfl_xor_sync(0xffffffffu, mx1, 1));
        mx1 = fmaxf(mx1, __shfl_xor_sync(0xffffffffu, mx1, 2));
        float nm0 = fmaxf(m0, mx0), nm1 = fmaxf(m1, mx1);
        float al0 = __expf(m0 - nm0), al1 = __expf(m1 - nm1);
        m0 = nm0; m1 = nm1;
        float sum0 = 0.f, sum1 = 0.f;
#pragma unroll
        for (int nt = 0; nt < 8; nt++) {
            s[nt].x = __expf(s[nt].x - m0); sum0 += s[nt].x;
            s[nt].y = __expf(s[nt].y - m0); sum0 += s[nt].y;
            s[nt].z = __expf(s[nt].z - m1); sum1 += s[nt].z;
            s[nt].w = __expf(s[nt].w - m1); sum1 += s[nt].w;
        }
        l0 = l0*al0 + sum0;
        l1 = l1*al1 + sum1;
#pragma unroll
        for (int dt = 0; dt < 4; dt++) {
            oacc[dt].x *= al0; oacc[dt].y *= al0;
            oacc[dt].z *= al1; oacc[dt].w *= al1;
        }
        __syncwarp();
#pragma unroll
        for (int nt = 0; nt < 8; nt++) {
            uint2 u0; u0.x = f2tf32(s[nt].x); u0.y = f2tf32(s[nt].y);
            uint2 u1; u1.x = f2tf32(s[nt].z); u1.y = f2tf32(s[nt].w);
            *(uint2*)&Ps[(r0  )*68 + nt*8 + 2*tig] = u0;
            *(uint2*)&Ps[(r0+8)*68 + nt*8 + 2*tig] = u1;
        }
        __syncwarp();
#pragma unroll
        for (int kt2 = 0; kt2 < 8; kt2++) {
            uint32_t a0 = Ps[(r0  )*68 + kt2*8 + tig];
            uint32_t a1 = Ps[(r0+8)*68 + kt2*8 + tig];
            uint32_t a2 = Ps[(r0  )*68 + kt2*8 + tig + 4];
            uint32_t a3 = Ps[(r0+8)*68 + kt2*8 + tig + 4];
#pragma unroll
            for (int dt = 0; dt < 4; dt++) {
                uint32_t b0 = Vs[(kb + kt2*8 + tig  )*40 + dt*8 + g];
                uint32_t b1 = Vs[(kb + kt2*8 + tig+4)*40 + dt*8 + g];
                mma_tf32(oacc[dt], a0, a1, a2, a3, b0, b1);
            }
        }
    }
    l0 += __shfl_xor_sync(0xffffffffu, l0, 1);
    l0 += __shfl_xor_sync(0xffffffffu, l0, 2);
    l1 += __shfl_xor_sync(0xffffffffu, l1, 1);
    l1 += __shfl_xor_sync(0xffffffffu, l1, 2);
    float inv0 = 1.f / l0, inv1 = 1.f / l1;
    float* ob = o + ((size_t)b*128 + h*32)*NP_FULL + p0;
#pragma unroll
    for (int dt = 0; dt < 4; dt++) {
        int d0 = dt*8 + 2*tig;
        ob[(size_t)(d0  )*NP_FULL + r0    ] = oacc[dt].x * inv0;
        ob[(size_t)(d0+1)*NP_FULL + r0    ] = oacc[dt].y * inv0;
        ob[(size_t)(d0  )*NP_FULL + r0 + 8] = oacc[dt].z * inv1;
        ob[(size_t)(d0+1)*NP_FULL + r0 + 8] = oacc[dt].w * inv1;
    }
}

// ---------------- high-frequency windowed attention: tf32 MMA ----------------
#define HSM_WORDS (24*576)
__global__ __launch_bounds__(256) void hattn_mma_k(
    const float* __restrict__ qkv, float* __restrict__ ho) {
    extern __shared__ uint32_t Hsm[];
    int b = blockIdx.y;
    int g0 = blockIdx.x * 2;
    const float* qb = qkv + (size_t)b*384*NP_FULL;
    int tid = threadIdx.x;
    for (int i = tid; i < 384*32; i += 256) {
        int c = i >> 5;
        int wt = i & 31;
        int win = wt >> 4, t = wt & 15;
        int which = c >> 7;
        int n = (c >> 5) & 3;
        int d = c & 31;
        int gg = g0 + win; int gy = gg / HGD, gx = gg - gy*HGD;
        int pp = (gy*4 + (t >> 2))*WW_ + gx*4 + (t & 3);
        float v = qb[(size_t)c*NP_FULL + pp];
        if (which == 0) v *= SCALE;
        Hsm[((win*4 + n)*3 + which)*576 + t*36 + d] = f2tf32(v);
    }
    __syncthreads();
    int lane = tid & 31, w = tid >> 5;
    int win = w >> 2, n = w & 3;
    int g = lane >> 2, tig = lane & 3;
    uint32_t* QB = Hsm + ((win*4 + n)*3 + 0)*576;
    uint32_t* KB = Hsm + ((win*4 + n)*3 + 1)*576;
    uint32_t* VB = Hsm + ((win*4 + n)*3 + 2)*576;
    float4 s[2];
    s[0] = make_float4(0.f,0.f,0.f,0.f);
    s[1] = make_float4(0.f,0.f,0.f,0.f);
#pragma unroll
    for (int ks = 0; ks < 32; ks += 8) {
        uint32_t a0 = QB[(g  )*36 + ks + tig];
        uint32_t a1 = QB[(g+8)*36 + ks + tig];
        uint32_t a2 = QB[(g  )*36 + ks + tig + 4];
        uint32_t a3 = QB[(g+8)*36 + ks + tig + 4];
#pragma unroll
        for (int nt = 0; nt < 2; nt++) {
            uint32_t b0 = KB[(nt*8+g)*36 + ks + tig];
            uint32_t b1 = KB[(nt*8+g)*36 + ks + tig + 4];
            mma_tf32(s[nt], a0, a1, a2, a3, b0, b1);
        }
    }
    float mx0 = fmaxf(fmaxf(s[0].x, s[0].y), fmaxf(s[1].x, s[1].y));
    float mx1 = fmaxf(fmaxf(s[0].z, s[0].w), fmaxf(s[1].z, s[1].w));
    mx0 = fmaxf(mx0, __shfl_xor_sync(0xffffffffu, mx0, 1));
    mx0 = fmaxf(mx0, __shfl_xor_sync(0xffffffffu, mx0, 2));
    mx1 = fmaxf(mx1, __shfl_xor_sync(0xffffffffu, mx1, 1));
    mx1 = fmaxf(mx1, __shfl_xor_sync(0xffffffffu, mx1, 2));
    float l0 = 0.f, l1 = 0.f;
#pragma unroll
    for (int nt = 0; nt < 2; nt++) {
        s[nt].x = __expf(s[nt].x - mx0); l0 += s[nt].x;
        s[nt].y = __expf(s[nt].y - mx0); l0 += s[nt].y;
        s[nt].z = __expf(s[nt].z - mx1); l1 += s[nt].z;
        s[nt].w = __expf(s[nt].w - mx1); l1 += s[nt].w;
    }
    l0 += __shfl_xor_sync(0xffffffffu, l0, 1);
    l0 += __shfl_xor_sync(0xffffffffu, l0, 2);
    l1 += __shfl_xor_sync(0xffffffffu, l1, 1);
    l1 += __shfl_xor_sync(0xffffffffu, l1, 2);
    float inv0 = 1.f / l0, inv1 = 1.f / l1;
    __syncwarp();
#pragma unroll
    for (int nt = 0; nt < 2; nt++) {
        QB[(g  )*36 + nt*8 + 2*tig    ] = f2tf32(s[nt].x * inv0);
        QB[(g  )*36 + nt*8 + 2*tig + 1] = f2tf32(s[nt].y * inv0);
        QB[(g+8)*36 + nt*8 + 2*tig    ] = f2tf32(s[nt].z * inv1);
        QB[(g+8)*36 + nt*8 + 2*tig + 1] = f2tf32(s[nt].w * inv1);
    }
    __syncwarp();
    float4 o[4];
#pragma unroll
    for (int dt = 0; dt < 4; dt++) o[dt] = make_float4(0.f,0.f,0.f,0.f);
#pragma unroll
    for (int ks = 0; ks < 16; ks += 8) {
        uint32_t a0 = QB[(g  )*36 + ks + tig];
        uint32_t a1 = QB[(g+8)*36 + ks + tig];
        uint32_t a2 = QB[(g  )*36 + ks + tig + 4];
        uint32_t a3 = QB[(g+8)*36 + ks + tig + 4];
#pragma unroll
        for (int dt = 0; dt < 4; dt++) {
            uint32_t b0 = VB[(ks+tig  )*36 + dt*8 + g];
            uint32_t b1 = VB[(ks+tig+4)*36 + dt*8 + g];
            mma_tf32(o[dt], a0, a1, a2, a3, b0, b1);
        }
    }
    int gw = g0 + win; int gy = gw / HGD, gx = gw - gy*HGD;
    int pbase = gy*4*WW_ + gx*4;
    int pp0 = pbase + ((g  ) >> 2)*WW_ + ((g  ) & 3);
    int pp1 = pbase + ((g+8) >> 2)*WW_ + ((g+8) & 3);
    float* ob = ho + (size_t)b*128*NP_FULL;
#pragma unroll
    for (int dt = 0; dt < 4; dt++) {
        int d = n*32 + dt*8 + 2*tig;
        ob[(size_t)(d  )*NP_FULL + pp0] = o[dt].x;
        ob[(size_t)(d+1)*NP_FULL + pp0] = o[dt].y;
        ob[(size_t)(d  )*NP_FULL + pp1] = o[dt].z;
        ob[(size_t)(d+1)*NP_FULL + pp1] = o[dt].w;
    }
}

// ---------------- launch ----------------
extern "C" void kernel_launch(void* const* d_in, const int* in_sizes, int n_in,
                              void* d_out, int out_size) {
    const float* x          = (const float*)d_in[0];
    const float* restore_w  = (const float*)d_in[1];
    const float* restore_b  = (const float*)d_in[2];
    const float* lq_dw_w    = (const float*)d_in[3];
    const float* lq_dw_b    = (const float*)d_in[4];
    const float* lq_pw_w    = (const float*)d_in[5];
    const float* lq_pw_b    = (const float*)d_in[6];
    const float* lkv_dw_w   = (const float*)d_in[7];
    const float* lkv_dw_b   = (const float*)d_in[8];
    const float* lkv_pw_w   = (const float*)d_in[9];
    const float* lkv_pw_b   = (const float*)d_in[10];
    const float* lproj_dw_w = (const float*)d_in[11];
    const float* lproj_dw_b = (const float*)d_in[12];
    const float* lproj_pw_w = (const float*)d_in[13];
    const float* lproj_pw_b = (const float*)d_in[14];
    const float* hqkv_dw_w  = (const float*)d_in[15];
    const float* hqkv_dw_b  = (const float*)d_in[16];
    const float* hqkv_pw_w  = (const float*)d_in[17];
    const float* hqkv_pw_b  = (const float*)d_in[18];
    const float* hproj_dw_w = (const float*)d_in[19];
    const float* hproj_dw_b = (const float*)d_in[20];
    const float* hproj_pw_w = (const float*)d_in[21];
    const float* hproj_pw_b = (const float*)d_in[22];
    float* out = (float*)d_out;

    float *low, *high, *dwA, *dwB, *lq, *lkvdw, *lkv, *lattn, *qkvb, *ho;
    cudaGetSymbolAddress((void**)&low,   g_low);
    cudaGetSymbolAddress((void**)&high,  g_high);
    cudaGetSymbolAddress((void**)&dwA,   g_dw);
    cudaGetSymbolAddress((void**)&dwB,   g_dw2);
    cudaGetSymbolAddress((void**)&lq,    g_lq);
    cudaGetSymbolAddress((void**)&lkvdw, g_lkvdw);
    cudaGetSymbolAddress((void**)&lkv,   g_lkv);
    cudaGetSymbolAddress((void**)&lattn, g_lattn);
    cudaGetSymbolAddress((void**)&qkvb,  g_qkv);
    cudaGetSymbolAddress((void**)&ho,    g_ho);

    static cudaStream_t s2 = nullptr, s3 = nullptr;
    static cudaEvent_t evFork = nullptr, evJoin = nullptr, evLkv = nullptr;
    if (!s2) {
        cudaStreamCreateWithFlags(&s2, cudaStreamNonBlocking);
        cudaStreamCreateWithFlags(&s3, cudaStreamNonBlocking);
        cudaEventCreateWithFlags(&evFork, cudaEventDisableTiming);
        cudaEventCreateWithFlags(&evJoin, cudaEventDisableTiming);
        cudaEventCreateWithFlags(&evLkv, cudaEventDisableTiming);
        cudaFuncSetAttribute(pw_mma_k, cudaFuncAttributeMaxDynamicSharedMemorySize, PW_SMEM);
        cudaFuncSetAttribute(lattn_mma_k, cudaFuncAttributeMaxDynamicSharedMemorySize, LSM_WORDS*4);
        cudaFuncSetAttribute(hattn_mma_k, cudaFuncAttributeMaxDynamicSharedMemorySize, HSM_WORDS*4);
    }

    // ---- stream 0: pool (feeds all chains) ----
    {
        int total = BB*CC*GP;
        pool_k<<<(total + 255)/256, 256, 0>>>(x, low);
    }
    cudaEventRecord(evFork, 0);
    cudaStreamWaitEvent(s2, evFork, 0);
    cudaStreamWaitEvent(s3, evFork, 0);

    // ======== LKV mini-chain on s3 ========
    {
        int total32 = BB*CC*GP/32;
        dw_k<<<(total32 + 255)/256, 256, 0, s3>>>(low, lkv_dw_w, lkv_dw_b, lkvdw, CC, HGD, HGD, total32);
    }
    pw_mma_k<<<dim3((GP + 127)/128, 2, BB), 256, PW_SMEM, s3>>>(lkvdw, lkv_pw_w, lkv_pw_b, lkv, 256, GP, 256, 0);
    cudaEventRecord(evLkv, s3);

    // ======== HIGH chain on s2 ========
    high_k<<<dim3(NP_FULL/256, BB, 8), 256, 0, s2>>>(x, low, restore_w, restore_b, high);
    {
        int total32 = BB*CC*NP_FULL/32;
        dw_k<<<(total32 + 255)/256, 256, 0, s2>>>(high, hqkv_dw_w, hqkv_dw_b, dwB, CC, HH_, WW_, total32);
    }
    pw_mma_k<<<dim3(NP_FULL/128, 3, BB), 256, PW_SMEM, s2>>>(dwB, hqkv_pw_w, hqkv_pw_b, qkvb, 256, NP_FULL, 384, 0);
    hattn_mma_k<<<dim3(GP/2, BB), 256, HSM_WORDS*4, s2>>>(qkvb, ho);
    {
        int total32 = BB*128*NP_FULL/32;
        dw_k<<<(total32 + 255)/256, 256, 0, s2>>>(ho, hproj_dw_w, hproj_dw_b, dwB, 128, HH_, WW_, total32);
    }
    pw_mma_k<<<dim3(NP_FULL/128, 1, BB), 256, PW_SMEM, s2>>>(dwB, hproj_pw_w, hproj_pw_b, out, 128, NP_FULL, 256, 128);
    cudaEventRecord(evJoin, s2);

    // ======== LOW chain on stream 0 ========
    {
        int total32 = BB*CC*NP_FULL/32;
        dw_k<<<(total32 + 255)/256, 256, 0>>>(x, lq_dw_w, lq_dw_b, dwA, CC, HH_, WW_, total32);
    }
    pw_mma_k<<<dim3(NP_FULL/128, 1, BB), 256, PW_SMEM>>>(dwA, lq_pw_w, lq_pw_b, lq, 256, NP_FULL, 128, 0);
    cudaStreamWaitEvent(0, evLkv, 0);
    lattn_mma_k<<<dim3(NP_FULL/128, 4, BB), 256, LSM_WORDS*4>>>(lq, lkv, lattn);
    {
        int total32 = BB*128*NP_FULL/32;
        dw_k<<<(total32 + 255)/256, 256, 0>>>(lattn, lproj_dw_w, lproj_dw_b, dwA, 128, HH_, WW_, total32);
    }
    pw_mma_k<<<dim3(NP_FULL/128, 1, BB), 256, PW_SMEM>>>(dwA, lproj_pw_w, lproj_pw_b, out, 128, NP_FULL, 256, 0);

    // ---- join ----
    cudaStreamWaitEvent(0, evJoin, 0);
}

// round 16
// speedup vs baseline: 1.2164x; 1.2164x over previous
#include <cuda_runtime.h>
#include <cuda_bf16.h>
#include <cstdint>

#define BB 8
#define CC 256
#define HH_ 96
#define WW_ 96
#define NP_FULL 9216   // 96*96
#define GP 576         // 24*24
#define HGD 24
#define SCALE 0.17677669529663688f   // 32^-0.5
#define KVT_WORDS 41728   // 32*584 + 576*40 per (b,h)

typedef unsigned long long ull;

__device__ __forceinline__ ull pack2(float x, float y) {
    ull r;
    asm("mov.b64 %0, {%1, %2};" : "=l"(r) : "f"(x), "f"(y));
    return r;
}
__device__ __forceinline__ void unpack2(ull v, float& x, float& y) {
    asm("mov.b64 {%0, %1}, %2;" : "=f"(x), "=f"(y) : "l"(v));
}
__device__ __forceinline__ ull fma2(ull a, ull b, ull c) {
    ull d;
    asm("fma.rn.f32x2 %0, %1, %2, %3;" : "=l"(d) : "l"(a), "l"(b), "l"(c));
    return d;
}
__device__ __forceinline__ uint32_t f2tf32(float x) {
    uint32_t r;
    asm("cvt.rna.tf32.f32 %0, %1;" : "=r"(r) : "f"(x));
    return r;
}
__device__ __forceinline__ void mma_tf32(float4& d,
    uint32_t a0, uint32_t a1, uint32_t a2, uint32_t a3,
    uint32_t b0, uint32_t b1) {
    asm volatile("mma.sync.aligned.m16n8k8.row.col.f32.tf32.tf32.f32 "
        "{%0,%1,%2,%3}, {%4,%5,%6,%7}, {%8,%9}, {%0,%1,%2,%3};"
        : "+f"(d.x), "+f"(d.y), "+f"(d.z), "+f"(d.w)
        : "r"(a0), "r"(a1), "r"(a2), "r"(a3), "r"(b0), "r"(b1));
}
__device__ __forceinline__ void cp16(uint32_t dst_smem, const float* src) {
    asm volatile("cp.async.cg.shared.global [%0], [%1], 16;"
                 :: "r"(dst_smem), "l"(src));
}
__device__ __forceinline__ void cp16z(uint32_t dst_smem, const float* src, int nbytes) {
    asm volatile("cp.async.cg.shared.global [%0], [%1], 16, %2;"
                 :: "r"(dst_smem), "l"(src), "r"(nbytes));
}

// ---------------- static scratch ----------------
__device__ float g_low[(size_t)BB*CC*GP];
__device__ float g_high[(size_t)BB*CC*NP_FULL];
__device__ float g_dw[(size_t)BB*CC*NP_FULL];
__device__ float g_dw2[(size_t)BB*CC*NP_FULL];
__device__ float g_lq[(size_t)BB*128*NP_FULL];
__device__ float g_lkvdw[(size_t)BB*CC*GP];
__device__ float g_lkv[(size_t)BB*CC*GP];
__device__ uint32_t g_kvt[(size_t)32*KVT_WORDS];
__device__ float g_lattn[(size_t)BB*128*NP_FULL];
__device__ float g_qkv[(size_t)BB*384*NP_FULL];
__device__ float g_ho[(size_t)BB*128*NP_FULL];

// ---------------- kernel 1: 4x4 avg pool ----------------
__global__ void pool_k(const float* __restrict__ x, float* __restrict__ low) {
    int i = blockIdx.x * blockDim.x + threadIdx.x;
    if (i >= BB*CC*GP) return;
    int g = i % GP; int bc = i / GP;
    int gy = g / HGD, gx = g % HGD;
    const float* xp = x + (size_t)bc*NP_FULL + (gy*4)*WW_ + gx*4;
    float s = 0.f;
#pragma unroll
    for (int r = 0; r < 4; r++) {
        float4 v = *(const float4*)(xp + r*WW_);
        s += (v.x + v.y) + (v.z + v.w);
    }
    low[i] = s * (1.0f/16.0f);
}

// ---------------- kernel 2: high = restore(pixelshuffle(low)) - x ----------------
// grid: (36 pixel-tiles, BB, 4 oc-chunks of 64)
__global__ void high_k(const float* __restrict__ x, const float* __restrict__ low,
                       const float* __restrict__ rw, const float* __restrict__ rb,
                       float* __restrict__ high) {
    __shared__ float ws[64*16];
    __shared__ float bs[64];
    int tid = threadIdx.x;
    int oc0 = blockIdx.z * 64;
    for (int i = tid; i < 64*16; i += 256) ws[i] = rw[oc0*16 + i];
    if (tid < 64) bs[tid] = rb[oc0 + tid];
    __syncthreads();
    int b = blockIdx.y;
    int p = blockIdx.x * 256 + tid;
    int h = p / WW_, w = p % WW_;
    int off = (h & 3)*4 + (w & 3);
    int g = (h >> 2)*HGD + (w >> 2);
    ull lv2[8];
#pragma unroll
    for (int ci = 0; ci < 8; ci++) {
        float a = low[((size_t)b*CC + (2*ci+0)*16 + off)*GP + g];
        float bb2 = low[((size_t)b*CC + (2*ci+1)*16 + off)*GP + g];
        lv2[ci] = pack2(a, bb2);
    }
    const float* xp = x + (size_t)b*CC*NP_FULL + (size_t)oc0*NP_FULL + p;
    float* hp = high + (size_t)b*CC*NP_FULL + (size_t)oc0*NP_FULL + p;
#pragma unroll 4
    for (int oc = 0; oc < 64; oc++) {
        const ull* wrow = (const ull*)&ws[oc*16];
        ull acc = 0ull;
#pragma unroll
        for (int ci = 0; ci < 8; ci++) acc = fma2(lv2[ci], wrow[ci], acc);
        float sx, sy; unpack2(acc, sx, sy);
        float s = bs[oc] + sx + sy;
        hp[(size_t)oc*NP_FULL] = s - xp[(size_t)oc*NP_FULL];
    }
}

// ---------------- kernel 3: depthwise 3x3 pad1, 8 cols x 2 rows per thread ----------------
__global__ void dw_k(const float* __restrict__ in, const float* __restrict__ w,
                     const float* __restrict__ bias, float* __restrict__ out,
                     int Ctot, int Hd, int Wd, int total16) {
    int i = blockIdx.x * blockDim.x + threadIdx.x;
    if (i >= total16) return;
    int w8 = Wd >> 3;
    int h2 = Hd >> 1;
    int xq = i % w8; int t = i / w8;
    int y2 = t % h2;
    int bcimg = t / h2;
    int c = bcimg % Ctot;
    int x0 = xq * 8;
    int y0 = y2 * 2;
    const float* ip = in + (size_t)bcimg * Hd * Wd;
    const float* wp = w + c*9;
    float wv[9];
#pragma unroll
    for (int k = 0; k < 9; k++) wv[k] = __ldg(wp + k);

    float r[4][10];   // rows y0-1 .. y0+2, columns x0-1 .. x0+8
#pragma unroll
    for (int rr = 0; rr < 4; rr++) {
        int yy = y0 + rr - 1;
        bool yok = (yy >= 0) && (yy < Hd);
        const float* row = ip + yy*Wd;
        if (yok) {
            float4 m0 = *(const float4*)(row + x0);
            float4 m1 = *(const float4*)(row + x0 + 4);
            r[rr][1] = m0.x; r[rr][2] = m0.y; r[rr][3] = m0.z; r[rr][4] = m0.w;
            r[rr][5] = m1.x; r[rr][6] = m1.y; r[rr][7] = m1.z; r[rr][8] = m1.w;
            if (x0 > 0) {
                float4 L = *(const float4*)(row + x0 - 4);
                r[rr][0] = L.w;
            } else r[rr][0] = 0.f;
            if (x0 + 8 < Wd) {
                float4 R = *(const float4*)(row + x0 + 8);
                r[rr][9] = R.x;
            } else r[rr][9] = 0.f;
        } else {
#pragma unroll
            for (int j = 0; j < 10; j++) r[rr][j] = 0.f;
        }
    }
    float bvv = bias[c];
    float a0[8], a1[8];
#pragma unroll
    for (int j = 0; j < 8; j++) { a0[j] = bvv; a1[j] = bvv; }
#pragma unroll
    for (int ky = 0; ky < 3; ky++) {
#pragma unroll
        for (int dx = 0; dx < 3; dx++) {
            float wc = wv[ky*3 + dx];
#pragma unroll
            for (int j = 0; j < 8; j++) {
                a0[j] = fmaf(wc, r[ky  ][j+dx], a0[j]);
                a1[j] = fmaf(wc, r[ky+1][j+dx], a1[j]);
            }
        }
    }
    float* op0 = out + (size_t)bcimg*Hd*Wd + (size_t)y0*Wd + x0;
    float* op1 = op0 + Wd;
    float4 v;
    v.x=a0[0]; v.y=a0[1]; v.z=a0[2]; v.w=a0[3]; *(float4*)(op0)     = v;
    v.x=a0[4]; v.y=a0[5]; v.z=a0[6]; v.w=a0[7]; *(float4*)(op0 + 4) = v;
    v.x=a1[0]; v.y=a1[1]; v.z=a1[2]; v.w=a1[3]; *(float4*)(op1)     = v;
    v.x=a1[4]; v.y=a1[5]; v.z=a1[6]; v.w=a1[7]; *(float4*)(op1 + 4) = v;
}

// ---------------- kvprep: pre-convert lkv into the lattn smem layout (tf32) ----------------
__global__ void kvprep_k(const float* __restrict__ lkv, uint32_t* __restrict__ kvt) {
    int i = blockIdx.x * 256 + threadIdx.x;
    if (i >= 32*KVT_WORDS) return;
    int bh = i / KVT_WORDS;
    int idx = i - bh*KVT_WORDS;
    int b = bh >> 2, h = bh & 3;
    const float* kvb = lkv + ((size_t)b*256 + h*32)*GP;
    float v = 0.f;
    if (idx < 18688) {
        int d = idx / 584, kp = idx - d*584;
        if (kp < 576) v = kvb[(size_t)d*GP + kp];
    } else {
        int j = idx - 18688;
        int kp = j / 40, d = j - kp*40;
        if (d < 32) v = kvb[(size_t)(128 + d)*GP + kp];
    }
    kvt[i] = f2tf32(v);
}

// ---------------- pointwise 1x1 conv: tf32 MMA + 2-stage cp.async ----------------
#define AW 36
#define BW 136
#define ABUF (128*AW)
#define BBUF (32*BW)
#define PW_SMEM ((2*ABUF + 2*BBUF)*4)
__global__ __launch_bounds__(256, 2) void pw_mma_k(
    const float* __restrict__ in, const float* __restrict__ wgt,
    const float* __restrict__ bias, float* __restrict__ out,
    int IC, int NP, int out_cstride, int out_coff) {
    extern __shared__ float S[];
    float* Af = S;
    float* Bf = S + 2*ABUF;
    uint32_t sbase = (uint32_t)__cvta_generic_to_shared(S);
    int b = blockIdx.z;
    int oc0 = blockIdx.y * 128;
    int p0 = blockIdx.x * 128;
    int tid = threadIdx.x;
    int lane = tid & 31, wid = tid >> 5;
    int wm = wid >> 2, wn = wid & 3;
    int g = lane >> 2, tig = lane & 3;
    const float* inb = in + (size_t)b * IC * NP;

    float4 acc[4][4];
#pragma unroll
    for (int i = 0; i < 4; i++)
#pragma unroll
        for (int j = 0; j < 4; j++) acc[i][j] = make_float4(0.f, 0.f, 0.f, 0.f);

    int a_oc = tid >> 1;
    int a_kb = (tid & 1) * 16;
    int b_kk = tid >> 3;
    int b_pb = (tid & 7) * 16;

    int NIT = IC >> 5;
    bool full = (p0 + 128 <= NP);

    const float* wr0 = wgt + (size_t)(oc0 + a_oc)*IC + a_kb;
    const float* br0 = inb + (size_t)b_kk*NP + p0 + b_pb;
    uint32_t adst0 = sbase + (a_oc*AW + a_kb)*4;
    uint32_t bdst0 = sbase + (2*ABUF + b_kk*BW + b_pb)*4;

    auto stage = [&](int buf, int it) {
        const float* wr = wr0 + it*32;
        uint32_t adst = adst0 + buf*(ABUF*4);
#pragma unroll
        for (int q = 0; q < 4; q++)
            cp16(adst + q*16, wr + q*4);
        const float* brow = br0 + (size_t)it*32*NP;
        uint32_t bdst = bdst0 + buf*(BBUF*4);
        if (full) {
#pragma unroll
            for (int q = 0; q < 4; q++)
                cp16(bdst + q*16, brow + q*4);
        } else {
            int pg = p0 + b_pb;
#pragma unroll
            for (int q = 0; q < 4; q++) {
                int rem = (NP - (pg + q*4)) * 4;
                int nb = rem >= 16 ? 16 : (rem > 0 ? rem : 0);
                const float* src = brow + q*4;
                if (nb == 0) src = inb;
                cp16z(bdst + q*16, src, nb);
            }
        }
    };

    stage(0, 0);
    asm volatile("cp.async.commit_group;");

    for (int it = 0; it < NIT; it++) {
        int buf = it & 1;
        if (it + 1 < NIT) {
            stage(buf ^ 1, it + 1);
            asm volatile("cp.async.commit_group;");
            asm volatile("cp.async.wait_group 1;");
        } else {
            asm volatile("cp.async.wait_group 0;");
        }
        __syncthreads();
        const float* Ab = Af + buf*ABUF;
        const float* Bb = Bf + buf*BBUF;
#pragma unroll
        for (int ks = 0; ks < 32; ks += 8) {
            uint32_t af[4][4];
#pragma unroll
            for (int mt = 0; mt < 4; mt++) {
                int oc = wm*64 + mt*16 + g;
                af[mt][0] = f2tf32(Ab[(oc  )*AW + ks + tig]);
                af[mt][1] = f2tf32(Ab[(oc+8)*AW + ks + tig]);
                af[mt][2] = f2tf32(Ab[(oc  )*AW + ks + tig + 4]);
                af[mt][3] = f2tf32(Ab[(oc+8)*AW + ks + tig + 4]);
            }
            uint32_t bf[4][2];
#pragma unroll
            for (int nt = 0; nt < 4; nt++) {
                int p = wn*32 + nt*8 + g;
                bf[nt][0] = f2tf32(Bb[(ks+tig  )*BW + p]);
                bf[nt][1] = f2tf32(Bb[(ks+tig+4)*BW + p]);
            }
#pragma unroll
            for (int mt = 0; mt < 4; mt++)
#pragma unroll
                for (int nt = 0; nt < 4; nt++)
                    mma_tf32(acc[mt][nt], af[mt][0], af[mt][1], af[mt][2], af[mt][3],
                             bf[nt][0], bf[nt][1]);
        }
        __syncthreads();
    }
    float* ob = out + (size_t)b * out_cstride * NP + (size_t)out_coff * NP;
#pragma unroll
    for (int mt = 0; mt < 4; mt++) {
        int r0 = oc0 + wm*64 + mt*16 + g;
        int r1 = r0 + 8;
        float bv0 = __ldg(bias + r0);
        float bv1 = __ldg(bias + r1);
        float* row0 = ob + (size_t)r0 * NP;
        float* row1 = ob + (size_t)r1 * NP;
#pragma unroll
        for (int nt = 0; nt < 4; nt++) {
            int c = p0 + wn*32 + nt*8 + tig*2;
            float4 a = acc[mt][nt];
            if (c + 1 < NP) {
                float2 v0; v0.x = a.x + bv0; v0.y = a.y + bv0;
                float2 v1; v1.x = a.z + bv1; v1.y = a.w + bv1;
                *(float2*)(row0 + c) = v0;
                *(float2*)(row1 + c) = v1;
            } else if (c < NP) {
                row0[c] = a.x + bv0;
                row1[c] = a.z + bv1;
            }
        }
    }
}

// ---------------- low-frequency global attention: flash tf32 MMA ----------------
// KV staged via one bulk cp.async copy from pre-converted g_kvt.
#define LSM_WORDS 50432
__global__ __launch_bounds__(256) void lattn_mma_k(
    const float* __restrict__ q, const uint32_t* __restrict__ kvt,
    float* __restrict__ o) {
    extern __shared__ uint32_t Su[];
    uint32_t* Ps = Su;
    uint32_t* Ks = Su + 8704;
    uint32_t* Vs = Su + 27392;
    int b = blockIdx.z, h = blockIdx.y;
    int p0 = blockIdx.x * 128;
    int tid = threadIdx.x;
    int lane = tid & 31, w = tid >> 5;
    int g = lane >> 2, tig = lane & 3;
    const float* qb  = q + ((size_t)b*128 + h*32)*NP_FULL;
    const uint32_t* kvb = kvt + (size_t)(b*4 + h)*KVT_WORDS;
    uint32_t sbase = (uint32_t)__cvta_generic_to_shared(Su);

    // bulk KV copy: 41728 words -> Su+8704 (Ks then Vs, contiguous)
    for (int i = tid*4; i < KVT_WORDS; i += 1024)
        cp16(sbase + (8704 + i)*4, (const float*)(kvb + i));
    asm volatile("cp.async.commit_group;");

    for (int i = tid; i < 128*32; i += 256) {
        int d = i >> 7, pix = i & 127;
        Ps[pix*36 + d] = f2tf32(qb[(size_t)d*NP_FULL + p0 + pix] * SCALE);
    }
    asm volatile("cp.async.wait_group 0;");
    __syncthreads();

    int r0 = w*16 + g;
    uint32_t aq[4][4];
#pragma unroll
    for (int kt = 0; kt < 4; kt++) {
        aq[kt][0] = Ps[(r0  )*36 + kt*8 + tig];
        aq[kt][1] = Ps[(r0+8)*36 + kt*8 + tig];
        aq[kt][2] = Ps[(r0  )*36 + kt*8 + tig + 4];
        aq[kt][3] = Ps[(r0+8)*36 + kt*8 + tig + 4];
    }
    __syncwarp();

    float4 oacc[4];
#pragma unroll
    for (int dt = 0; dt < 4; dt++) oacc[dt] = make_float4(0.f,0.f,0.f,0.f);
    float m0 = -1e30f, m1 = -1e30f, l0 = 0.f, l1 = 0.f;

    for (int c = 0; c < 9; c++) {
        int kb = c*64;
        float4 s[8];
#pragma unroll
        for (int nt = 0; nt < 8; nt++) s[nt] = make_float4(0.f,0.f,0.f,0.f);
#pragma unroll
        for (int kt = 0; kt < 4; kt++) {
#pragma unroll
            for (int nt = 0; nt < 8; nt++) {
                uint32_t b0 = Ks[(kt*8+tig  )*584 + kb + nt*8 + g];
                uint32_t b1 = Ks[(kt*8+tig+4)*584 + kb + nt*8 + g];
                mma_tf32(s[nt], aq[kt][0], aq[kt][1], aq[kt][2], aq[kt][3], b0, b1);
            }
        }
        float mx0 = -1e30f, mx1 = -1e30f;
#pragma unroll
        for (int nt = 0; nt < 8; nt++) {
            mx0 = fmaxf(mx0, fmaxf(s[nt].x, s[nt].y));
            mx1 = fmaxf(mx1, fmaxf(s[nt].z, s[nt].w));
        }
        mx0 = fmaxf(mx0, __shfl_xor_sync(0xffffffffu, mx0, 1));
        mx0 = fmaxf(mx0, __shfl_xor_sync(0xffffffffu, mx0, 2));
        mx1 = fmaxf(mx1, __shfl_xor_sync(0xffffffffu, mx1, 1));
        mx1 = fmaxf(mx1, __shfl_xor_sync(0xffffffffu, mx1, 2));
        float nm0 = fmaxf(m0, mx0), nm1 = fmaxf(m1, mx1);
        float al0 = __expf(m0 - nm0), al1 = __expf(m1 - nm1);
        m0 = nm0; m1 = nm1;
        float sum0 = 0.f, sum1 = 0.f;
#pragma unroll
        for (int nt = 0; nt < 8; nt++) {
            s[nt].x = __expf(s[nt].x - m0); sum0 += s[nt].x;
            s[nt].y = __expf(s[nt].y - m0); sum0 += s[nt].y;
            s[nt].z = __expf(s[nt].z - m1); sum1 += s[nt].z;
            s[nt].w = __expf(s[nt].w - m1); sum1 += s[nt].w;
        }
        l0 = l0*al0 + sum0;
        l1 = l1*al1 + sum1;
#pragma unroll
        for (int dt = 0; dt < 4; dt++) {
            oacc[dt].x *= al0; oacc[dt].y *= al0;
            oacc[dt].z *= al1; oacc[dt].w *= al1;
        }
        __syncwarp();
#pragma unroll
        for (int nt = 0; nt < 8; nt++) {
            uint2 u0; u0.x = f2tf32(s[nt].x); u0.y = f2tf32(s[nt].y);
            uint2 u1; u1.x = f2tf32(s[nt].z); u1.y = f2tf32(s[nt].w);
            *(uint2*)&Ps[(r0  )*68 + nt*8 + 2*tig] = u0;
            *(uint2*)&Ps[(r0+8)*68 + nt*8 + 2*tig] = u1;
        }
        __syncwarp();
#pragma unroll
        for (int kt2 = 0; kt2 < 8; kt2++) {
            uint32_t a0 = Ps[(r0  )*68 + kt2*8 + tig];
            uint32_t a1 = Ps[(r0+8)*68 + kt2*8 + tig];
            uint32_t a2 = Ps[(r0  )*68 + kt2*8 + tig + 4];
            uint32_t a3 = Ps[(r0+8)*68 + kt2*8 + tig + 4];
#pragma unroll
            for (int dt = 0; dt < 4; dt++) {
                uint32_t b0 = Vs[(kb + kt2*8 + tig  )*40 + dt*8 + g];
                uint32_t b1 = Vs[(kb + kt2*8 + tig+4)*40 + dt*8 + g];
                mma_tf32(oacc[dt], a0, a1, a2, a3, b0, b1);
            }
        }
    }
    l0 += __shfl_xor_sync(0xffffffffu, l0, 1);
    l0 += __shfl_xor_sync(0xffffffffu, l0, 2);
    l1 += __shfl_xor_sync(0xffffffffu, l1, 1);
    l1 += __shfl_xor_sync(0xffffffffu, l1, 2);
    float inv0 = 1.f / l0, inv1 = 1.f / l1;
    float* ob = o + ((size_t)b*128 + h*32)*NP_FULL + p0;
#pragma unroll
    for (int dt = 0; dt < 4; dt++) {
        int d0 = dt*8 + 2*tig;
        ob[(size_t)(d0  )*NP_FULL + r0    ] = oacc[dt].x * inv0;
        ob[(size_t)(d0+1)*NP_FULL + r0    ] = oacc[dt].y * inv0;
        ob[(size_t)(d0  )*NP_FULL + r0 + 8] = oacc[dt].z * inv1;
        ob[(size_t)(d0+1)*NP_FULL + r0 + 8] = oacc[dt].w * inv1;
    }
}

// ---------------- high-frequency windowed attention: tf32 MMA ----------------
#define HSM_WORDS (24*576)
__global__ __launch_bounds__(256) void hattn_mma_k(
    const float* __restrict__ qkv, float* __restrict__ ho) {
    extern __shared__ uint32_t Hsm[];
    int b = blockIdx.y;
    int g0 = blockIdx.x * 2;
    const float* qb = qkv + (size_t)b*384*NP_FULL;
    int tid = threadIdx.x;
    for (int i = tid; i < 384*32; i += 256) {
        int c = i >> 5;
        int wt = i & 31;
        int win = wt >> 4, t = wt & 15;
        int which = c >> 7;
        int n = (c >> 5) & 3;
        int d = c & 31;
        int gg = g0 + win; int gy = gg / HGD, gx = gg - gy*HGD;
        int pp = (gy*4 + (t >> 2))*WW_ + gx*4 + (t & 3);
        float v = qb[(size_t)c*NP_FULL + pp];
        if (which == 0) v *= SCALE;
        Hsm[((win*4 + n)*3 + which)*576 + t*36 + d] = f2tf32(v);
    }
    __syncthreads();
    int lane = tid & 31, w = tid >> 5;
    int win = w >> 2, n = w & 3;
    int g = lane >> 2, tig = lane & 3;
    uint32_t* QB = Hsm + ((win*4 + n)*3 + 0)*576;
    uint32_t* KB = Hsm + ((win*4 + n)*3 + 1)*576;
    uint32_t* VB = Hsm + ((win*4 + n)*3 + 2)*576;
    float4 s[2];
    s[0] = make_float4(0.f,0.f,0.f,0.f);
    s[1] = make_float4(0.f,0.f,0.f,0.f);
#pragma unroll
    for (int ks = 0; ks < 32; ks += 8) {
        uint32_t a0 = QB[(g  )*36 + ks + tig];
        uint32_t a1 = QB[(g+8)*36 + ks + tig];
        uint32_t a2 = QB[(g  )*36 + ks + tig + 4];
        uint32_t a3 = QB[(g+8)*36 + ks + tig + 4];
#pragma unroll
        for (int nt = 0; nt < 2; nt++) {
            uint32_t b0 = KB[(nt*8+g)*36 + ks + tig];
            uint32_t b1 = KB[(nt*8+g)*36 + ks + tig + 4];
            mma_tf32(s[nt], a0, a1, a2, a3, b0, b1);
        }
    }
    float mx0 = fmaxf(fmaxf(s[0].x, s[0].y), fmaxf(s[1].x, s[1].y));
    float mx1 = fmaxf(fmaxf(s[0].z, s[0].w), fmaxf(s[1].z, s[1].w));
    mx0 = fmaxf(mx0, __shfl_xor_sync(0xffffffffu, mx0, 1));
    mx0 = fmaxf(mx0, __shfl_xor_sync(0xffffffffu, mx0, 2));
    mx1 = fmaxf(mx1, __shfl_xor_sync(0xffffffffu, mx1, 1));
    mx1 = fmaxf(mx1, __shfl_xor_sync(0xffffffffu, mx1, 2));
    float l0 = 0.f, l1 = 0.f;
#pragma unroll
    for (int nt = 0; nt < 2; nt++) {
        s[nt].x = __expf(s[nt].x - mx0); l0 += s[nt].x;
        s[nt].y = __expf(s[nt].y - mx0); l0 += s[nt].y;
        s[nt].z = __expf(s[nt].z - mx1); l1 += s[nt].z;
        s[nt].w = __expf(s[nt].w - mx1); l1 += s[nt].w;
    }
    l0 += __shfl_xor_sync(0xffffffffu, l0, 1);
    l0 += __shfl_xor_sync(0xffffffffu, l0, 2);
    l1 += __shfl_xor_sync(0xffffffffu, l1, 1);
    l1 += __shfl_xor_sync(0xffffffffu, l1, 2);
    float inv0 = 1.f / l0, inv1 = 1.f / l1;
    __syncwarp();
#pragma unroll
    for (int nt = 0; nt < 2; nt++) {
        QB[(g  )*36 + nt*8 + 2*tig    ] = f2tf32(s[nt].x * inv0);
        QB[(g  )*36 + nt*8 + 2*tig + 1] = f2tf32(s[nt].y * inv0);
        QB[(g+8)*36 + nt*8 + 2*tig    ] = f2tf32(s[nt].z * inv1);
        QB[(g+8)*36 + nt*8 + 2*tig + 1] = f2tf32(s[nt].w * inv1);
    }
    __syncwarp();
    float4 o[4];
#pragma unroll
    for (int dt = 0; dt < 4; dt++) o[dt] = make_float4(0.f,0.f,0.f,0.f);
#pragma unroll
    for (int ks = 0; ks < 16; ks += 8) {
        uint32_t a0 = QB[(g  )*36 + ks + tig];
        uint32_t a1 = QB[(g+8)*36 + ks + tig];
        uint32_t a2 = QB[(g  )*36 + ks + tig + 4];
        uint32_t a3 = QB[(g+8)*36 + ks + tig + 4];
#pragma unroll
        for (int dt = 0; dt < 4; dt++) {
            uint32_t b0 = VB[(ks+tig  )*36 + dt*8 + g];
            uint32_t b1 = VB[(ks+tig+4)*36 + dt*8 + g];
            mma_tf32(o[dt], a0, a1, a2, a3, b0, b1);
        }
    }
    int gw = g0 + win; int gy = gw / HGD, gx = gw - gy*HGD;
    int pbase = gy*4*WW_ + gx*4;
    int pp0 = pbase + ((g  ) >> 2)*WW_ + ((g  ) & 3);
    int pp1 = pbase + ((g+8) >> 2)*WW_ + ((g+8) & 3);
    float* ob = ho + (size_t)b*128*NP_FULL;
#pragma unroll
    for (int dt = 0; dt < 4; dt++) {
        int d = n*32 + dt*8 + 2*tig;
        ob[(size_t)(d  )*NP_FULL + pp0] = o[dt].x;
        ob[(size_t)(d+1)*NP_FULL + pp0] = o[dt].y;
        ob[(size_t)(d  )*NP_FULL + pp1] = o[dt].z;
        ob[(size_t)(d+1)*NP_FULL + pp1] = o[dt].w;
    }
}

// ---------------- launch ----------------
extern "C" void kernel_launch(void* const* d_in, const int* in_sizes, int n_in,
                              void* d_out, int out_size) {
    const float* x          = (const float*)d_in[0];
    const float* restore_w  = (const float*)d_in[1];
    const float* restore_b  = (const float*)d_in[2];
    const float* lq_dw_w    = (const float*)d_in[3];
    const float* lq_dw_b    = (const float*)d_in[4];
    const float* lq_pw_w    = (const float*)d_in[5];
    const float* lq_pw_b    = (const float*)d_in[6];
    const float* lkv_dw_w   = (const float*)d_in[7];
    const float* lkv_dw_b   = (const float*)d_in[8];
    const float* lkv_pw_w   = (const float*)d_in[9];
    const float* lkv_pw_b   = (const float*)d_in[10];
    const float* lproj_dw_w = (const float*)d_in[11];
    const float* lproj_dw_b = (const float*)d_in[12];
    const float* lproj_pw_w = (const float*)d_in[13];
    const float* lproj_pw_b = (const float*)d_in[14];
    const float* hqkv_dw_w  = (const float*)d_in[15];
    const float* hqkv_dw_b  = (const float*)d_in[16];
    const float* hqkv_pw_w  = (const float*)d_in[17];
    const float* hqkv_pw_b  = (const float*)d_in[18];
    const float* hproj_dw_w = (const float*)d_in[19];
    const float* hproj_dw_b = (const float*)d_in[20];
    const float* hproj_pw_w = (const float*)d_in[21];
    const float* hproj_pw_b = (const float*)d_in[22];
    float* out = (float*)d_out;

    float *low, *high, *dwA, *dwB, *lq, *lkvdw, *lkv, *lattn, *qkvb, *ho;
    uint32_t* kvt;
    cudaGetSymbolAddress((void**)&low,   g_low);
    cudaGetSymbolAddress((void**)&high,  g_high);
    cudaGetSymbolAddress((void**)&dwA,   g_dw);
    cudaGetSymbolAddress((void**)&dwB,   g_dw2);
    cudaGetSymbolAddress((void**)&lq,    g_lq);
    cudaGetSymbolAddress((void**)&lkvdw, g_lkvdw);
    cudaGetSymbolAddress((void**)&lkv,   g_lkv);
    cudaGetSymbolAddress((void**)&kvt,   g_kvt);
    cudaGetSymbolAddress((void**)&lattn, g_lattn);
    cudaGetSymbolAddress((void**)&qkvb,  g_qkv);
    cudaGetSymbolAddress((void**)&ho,    g_ho);

    static cudaStream_t s2 = nullptr, s3 = nullptr;
    static cudaEvent_t evFork = nullptr, evJoin = nullptr, evLkv = nullptr;
    if (!s2) {
        cudaStreamCreateWithFlags(&s2, cudaStreamNonBlocking);
        cudaStreamCreateWithFlags(&s3, cudaStreamNonBlocking);
        cudaEventCreateWithFlags(&evFork, cudaEventDisableTiming);
        cudaEventCreateWithFlags(&evJoin, cudaEventDisableTiming);
        cudaEventCreateWithFlags(&evLkv, cudaEventDisableTiming);
        cudaFuncSetAttribute(pw_mma_k, cudaFuncAttributeMaxDynamicSharedMemorySize, PW_SMEM);
        cudaFuncSetAttribute(lattn_mma_k, cudaFuncAttributeMaxDynamicSharedMemorySize, LSM_WORDS*4);
        cudaFuncSetAttribute(hattn_mma_k, cudaFuncAttributeMaxDynamicSharedMemorySize, HSM_WORDS*4);
    }

    // ---- stream 0: pool (feeds all chains) ----
    {
        int total = BB*CC*GP;
        pool_k<<<(total + 255)/256, 256, 0>>>(x, low);
    }
    cudaEventRecord(evFork, 0);
    cudaStreamWaitEvent(s2, evFork, 0);
    cudaStreamWaitEvent(s3, evFork, 0);

    // ======== LKV mini-chain on s3 ========
    {
        int total16 = BB*CC*GP/16;
        dw_k<<<(total16 + 255)/256, 256, 0, s3>>>(low, lkv_dw_w, lkv_dw_b, lkvdw, CC, HGD, HGD, total16);
    }
    pw_mma_k<<<dim3((GP + 127)/128, 2, BB), 256, PW_SMEM, s3>>>(lkvdw, lkv_pw_w, lkv_pw_b, lkv, 256, GP, 256, 0);
    {
        int total = 32*KVT_WORDS;
        kvprep_k<<<(total + 255)/256, 256, 0, s3>>>(lkv, kvt);
    }
    cudaEventRecord(evLkv, s3);

    // ======== HIGH chain on s2 ========
    high_k<<<dim3(NP_FULL/256, BB, 4), 256, 0, s2>>>(x, low, restore_w, restore_b, high);
    {
        int total16 = BB*CC*NP_FULL/16;
        dw_k<<<(total16 + 255)/256, 256, 0, s2>>>(high, hqkv_dw_w, hqkv_dw_b, dwB, CC, HH_, WW_, total16);
    }
    pw_mma_k<<<dim3(NP_FULL/128, 3, BB), 256, PW_SMEM, s2>>>(dwB, hqkv_pw_w, hqkv_pw_b, qkvb, 256, NP_FULL, 384, 0);
    hattn_mma_k<<<dim3(GP/2, BB), 256, HSM_WORDS*4, s2>>>(qkvb, ho);
    {
        int total16 = BB*128*NP_FULL/16;
        dw_k<<<(total16 + 255)/256, 256, 0, s2>>>(ho, hproj_dw_w, hproj_dw_b, dwB, 128, HH_, WW_, total16);
    }
    pw_mma_k<<<dim3(NP_FULL/128, 1, BB), 256, PW_SMEM, s2>>>(dwB, hproj_pw_w, hproj_pw_b, out, 128, NP_FULL, 256, 128);
    cudaEventRecord(evJoin, s2);

    // ======== LOW chain on stream 0 ========
    {
        int total16 = BB*CC*NP_FULL/16;
        dw_k<<<(total16 + 255)/256, 256, 0>>>(x, lq_dw_w, lq_dw_b, dwA, CC, HH_, WW_, total16);
    }
    pw_mma_k<<<dim3(NP_FULL/128, 1, BB), 256, PW_SMEM>>>(dwA, lq_pw_w, lq_pw_b, lq, 256, NP_FULL, 128, 0);
    cudaStreamWaitEvent(0, evLkv, 0);
    lattn_mma_k<<<dim3(NP_FULL/128, 4, BB), 256, LSM_WORDS*4>>>(lq, kvt, lattn);
    {
        int total16 = BB*128*NP_FULL/16;
        dw_k<<<(total16 + 255)/256, 256, 0>>>(lattn, lproj_dw_w, lproj_dw_b, dwA, 128, HH_, WW_, total16);
    }
    pw_mma_k<<<dim3(NP_FULL/128, 1, BB), 256, PW_SMEM>>>(dwA, lproj_pw_w, lproj_pw_b, out, 128, NP_FULL, 256, 0);

    // ---- join ----
    cudaStreamWaitEvent(0, evJoin, 0);
}

// round 17
// speedup vs baseline: 1.2425x; 1.0215x over previous
#include <cuda_runtime.h>
#include <cuda_bf16.h>
#include <cstdint>

#define BB 8
#define CC 256
#define HH_ 96
#define WW_ 96
#define NP_FULL 9216   // 96*96
#define GP 576         // 24*24
#define HGD 24
#define SCALE 0.17677669529663688f   // 32^-0.5
#define KVT_WORDS 41728   // 32*584 + 576*40 per (b,h)

// weight-table offsets (tf32 words)
#define WT_LQ    0
#define WT_LKV   32768
#define WT_LPROJ 98304
#define WT_HQKV  114688
#define WT_HPROJ 212992
#define WT_TOTAL 229376

typedef unsigned long long ull;

__device__ __forceinline__ ull pack2(float x, float y) {
    ull r;
    asm("mov.b64 %0, {%1, %2};" : "=l"(r) : "f"(x), "f"(y));
    return r;
}
__device__ __forceinline__ void unpack2(ull v, float& x, float& y) {
    asm("mov.b64 {%0, %1}, %2;" : "=f"(x), "=f"(y) : "l"(v));
}
__device__ __forceinline__ ull fma2(ull a, ull b, ull c) {
    ull d;
    asm("fma.rn.f32x2 %0, %1, %2, %3;" : "=l"(d) : "l"(a), "l"(b), "l"(c));
    return d;
}
__device__ __forceinline__ uint32_t f2tf32(float x) {
    uint32_t r;
    asm("cvt.rna.tf32.f32 %0, %1;" : "=r"(r) : "f"(x));
    return r;
}
__device__ __forceinline__ void mma_tf32(float4& d,
    uint32_t a0, uint32_t a1, uint32_t a2, uint32_t a3,
    uint32_t b0, uint32_t b1) {
    asm volatile("mma.sync.aligned.m16n8k8.row.col.f32.tf32.tf32.f32 "
        "{%0,%1,%2,%3}, {%4,%5,%6,%7}, {%8,%9}, {%0,%1,%2,%3};"
        : "+f"(d.x), "+f"(d.y), "+f"(d.z), "+f"(d.w)
        : "r"(a0), "r"(a1), "r"(a2), "r"(a3), "r"(b0), "r"(b1));
}
__device__ __forceinline__ void cp16(uint32_t dst_smem, const void* src) {
    asm volatile("cp.async.cg.shared.global [%0], [%1], 16;"
                 :: "r"(dst_smem), "l"(src));
}
__device__ __forceinline__ void cp16z(uint32_t dst_smem, const void* src, int nbytes) {
    asm volatile("cp.async.cg.shared.global [%0], [%1], 16, %2;"
                 :: "r"(dst_smem), "l"(src), "r"(nbytes));
}

// ---------------- static scratch ----------------
__device__ float g_low[(size_t)BB*CC*GP];
__device__ float g_high[(size_t)BB*CC*NP_FULL];
__device__ float g_dw[(size_t)BB*CC*NP_FULL];     // holds tf32 bits
__device__ float g_dw2[(size_t)BB*CC*NP_FULL];    // holds tf32 bits
__device__ float g_lkvdw[(size_t)BB*CC*GP];       // tf32 bits
__device__ uint32_t g_wt[WT_TOTAL];
__device__ float g_lq[(size_t)BB*128*NP_FULL];
__device__ float g_lkv[(size_t)BB*CC*GP];
__device__ uint32_t g_kvt[(size_t)32*KVT_WORDS];
__device__ float g_lattn[(size_t)BB*128*NP_FULL];
__device__ float g_qkv[(size_t)BB*384*NP_FULL];
__device__ float g_ho[(size_t)BB*128*NP_FULL];

// ---------------- weight cvt: fp32 -> tf32 bits ----------------
__global__ void wcvt_k(const float* __restrict__ src, uint32_t* __restrict__ dst, int n) {
    int i = blockIdx.x * 256 + threadIdx.x;
    if (i < n) dst[i] = f2tf32(src[i]);
}

// ---------------- kernel 1: 4x4 avg pool ----------------
__global__ void pool_k(const float* __restrict__ x, float* __restrict__ low) {
    int i = blockIdx.x * blockDim.x + threadIdx.x;
    if (i >= BB*CC*GP) return;
    int g = i % GP; int bc = i / GP;
    int gy = g / HGD, gx = g % HGD;
    const float* xp = x + (size_t)bc*NP_FULL + (gy*4)*WW_ + gx*4;
    float s = 0.f;
#pragma unroll
    for (int r = 0; r < 4; r++) {
        float4 v = *(const float4*)(xp + r*WW_);
        s += (v.x + v.y) + (v.z + v.w);
    }
    low[i] = s * (1.0f/16.0f);
}

// ---------------- kernel 2: high = restore(pixelshuffle(low)) - x ----------------
__global__ void high_k(const float* __restrict__ x, const float* __restrict__ low,
                       const float* __restrict__ rw, const float* __restrict__ rb,
                       float* __restrict__ high) {
    __shared__ float ws[64*16];
    __shared__ float bs[64];
    int tid = threadIdx.x;
    int oc0 = blockIdx.z * 64;
    for (int i = tid; i < 64*16; i += 256) ws[i] = rw[oc0*16 + i];
    if (tid < 64) bs[tid] = rb[oc0 + tid];
    __syncthreads();
    int b = blockIdx.y;
    int p = blockIdx.x * 256 + tid;
    int h = p / WW_, w = p % WW_;
    int off = (h & 3)*4 + (w & 3);
    int g = (h >> 2)*HGD + (w >> 2);
    ull lv2[8];
#pragma unroll
    for (int ci = 0; ci < 8; ci++) {
        float a = low[((size_t)b*CC + (2*ci+0)*16 + off)*GP + g];
        float bb2 = low[((size_t)b*CC + (2*ci+1)*16 + off)*GP + g];
        lv2[ci] = pack2(a, bb2);
    }
    const float* xp = x + (size_t)b*CC*NP_FULL + (size_t)oc0*NP_FULL + p;
    float* hp = high + (size_t)b*CC*NP_FULL + (size_t)oc0*NP_FULL + p;
#pragma unroll 4
    for (int oc = 0; oc < 64; oc++) {
        const ull* wrow = (const ull*)&ws[oc*16];
        ull acc = 0ull;
#pragma unroll
        for (int ci = 0; ci < 8; ci++) acc = fma2(lv2[ci], wrow[ci], acc);
        float sx, sy; unpack2(acc, sx, sy);
        float s = bs[oc] + sx + sy;
        hp[(size_t)oc*NP_FULL] = s - xp[(size_t)oc*NP_FULL];
    }
}

// ---------------- kernel 3: depthwise 3x3 pad1, stores tf32 bits ----------------
__global__ void dw_k(const float* __restrict__ in, const float* __restrict__ w,
                     const float* __restrict__ bias, float* __restrict__ out,
                     int Ctot, int Hd, int Wd, int total16) {
    int i = blockIdx.x * blockDim.x + threadIdx.x;
    if (i >= total16) return;
    int w8 = Wd >> 3;
    int h2 = Hd >> 1;
    int xq = i % w8; int t = i / w8;
    int y2 = t % h2;
    int bcimg = t / h2;
    int c = bcimg % Ctot;
    int x0 = xq * 8;
    int y0 = y2 * 2;
    const float* ip = in + (size_t)bcimg * Hd * Wd;
    const float* wp = w + c*9;
    float wv[9];
#pragma unroll
    for (int k = 0; k < 9; k++) wv[k] = __ldg(wp + k);

    float r[4][10];
#pragma unroll
    for (int rr = 0; rr < 4; rr++) {
        int yy = y0 + rr - 1;
        bool yok = (yy >= 0) && (yy < Hd);
        const float* row = ip + yy*Wd;
        if (yok) {
            float4 m0 = *(const float4*)(row + x0);
            float4 m1 = *(const float4*)(row + x0 + 4);
            r[rr][1] = m0.x; r[rr][2] = m0.y; r[rr][3] = m0.z; r[rr][4] = m0.w;
            r[rr][5] = m1.x; r[rr][6] = m1.y; r[rr][7] = m1.z; r[rr][8] = m1.w;
            if (x0 > 0) {
                float4 L = *(const float4*)(row + x0 - 4);
                r[rr][0] = L.w;
            } else r[rr][0] = 0.f;
            if (x0 + 8 < Wd) {
                float4 R = *(const float4*)(row + x0 + 8);
                r[rr][9] = R.x;
            } else r[rr][9] = 0.f;
        } else {
#pragma unroll
            for (int j = 0; j < 10; j++) r[rr][j] = 0.f;
        }
    }
    float bvv = bias[c];
    float a0[8], a1[8];
#pragma unroll
    for (int j = 0; j < 8; j++) { a0[j] = bvv; a1[j] = bvv; }
#pragma unroll
    for (int ky = 0; ky < 3; ky++) {
#pragma unroll
        for (int dx = 0; dx < 3; dx++) {
            float wc = wv[ky*3 + dx];
#pragma unroll
            for (int j = 0; j < 8; j++) {
                a0[j] = fmaf(wc, r[ky  ][j+dx], a0[j]);
                a1[j] = fmaf(wc, r[ky+1][j+dx], a1[j]);
            }
        }
    }
    float* op0 = out + (size_t)bcimg*Hd*Wd + (size_t)y0*Wd + x0;
    float* op1 = op0 + Wd;
    float4 v;
    v.x=__uint_as_float(f2tf32(a0[0])); v.y=__uint_as_float(f2tf32(a0[1]));
    v.z=__uint_as_float(f2tf32(a0[2])); v.w=__uint_as_float(f2tf32(a0[3]));
    *(float4*)(op0) = v;
    v.x=__uint_as_float(f2tf32(a0[4])); v.y=__uint_as_float(f2tf32(a0[5]));
    v.z=__uint_as_float(f2tf32(a0[6])); v.w=__uint_as_float(f2tf32(a0[7]));
    *(float4*)(op0 + 4) = v;
    v.x=__uint_as_float(f2tf32(a1[0])); v.y=__uint_as_float(f2tf32(a1[1]));
    v.z=__uint_as_float(f2tf32(a1[2])); v.w=__uint_as_float(f2tf32(a1[3]));
    *(float4*)(op1) = v;
    v.x=__uint_as_float(f2tf32(a1[4])); v.y=__uint_as_float(f2tf32(a1[5]));
    v.z=__uint_as_float(f2tf32(a1[6])); v.w=__uint_as_float(f2tf32(a1[7]));
    *(float4*)(op1 + 4) = v;
}

// ---------------- kvprep: pre-convert lkv into the lattn smem layout (tf32) ----------------
__global__ void kvprep_k(const float* __restrict__ lkv, uint32_t* __restrict__ kvt) {
    int i = blockIdx.x * 256 + threadIdx.x;
    if (i >= 32*KVT_WORDS) return;
    int bh = i / KVT_WORDS;
    int idx = i - bh*KVT_WORDS;
    int b = bh >> 2, h = bh & 3;
    const float* kvb = lkv + ((size_t)b*256 + h*32)*GP;
    float v = 0.f;
    if (idx < 18688) {
        int d = idx / 584, kp = idx - d*584;
        if (kp < 576) v = kvb[(size_t)d*GP + kp];
    } else {
        int j = idx - 18688;
        int kp = j / 40, d = j - kp*40;
        if (d < 32) v = kvb[(size_t)(128 + d)*GP + kp];
    }
    kvt[i] = f2tf32(v);
}

// ---------------- pointwise 1x1 conv: tf32 MMA, inputs pre-converted ----------------
#define AW 36
#define BW 136
#define ABUF (128*AW)
#define BBUF (32*BW)
#define PW_SMEM ((2*ABUF + 2*BBUF)*4)
__global__ __launch_bounds__(256, 2) void pw_mma_k(
    const float* __restrict__ in, const uint32_t* __restrict__ wgt,
    const float* __restrict__ bias, float* __restrict__ out,
    int IC, int NP, int out_cstride, int out_coff) {
    extern __shared__ uint32_t S[];
    uint32_t* Af = S;
    uint32_t* Bf = S + 2*ABUF;
    uint32_t sbase = (uint32_t)__cvta_generic_to_shared(S);
    int b = blockIdx.z;
    int oc0 = blockIdx.y * 128;
    int p0 = blockIdx.x * 128;
    int tid = threadIdx.x;
    int lane = tid & 31, wid = tid >> 5;
    int wm = wid >> 2, wn = wid & 3;
    int g = lane >> 2, tig = lane & 3;
    const float* inb = in + (size_t)b * IC * NP;

    float4 acc[4][4];
#pragma unroll
    for (int i = 0; i < 4; i++)
#pragma unroll
        for (int j = 0; j < 4; j++) acc[i][j] = make_float4(0.f, 0.f, 0.f, 0.f);

    int a_oc = tid >> 1;
    int a_kb = (tid & 1) * 16;
    int b_kk = tid >> 3;
    int b_pb = (tid & 7) * 16;

    int NIT = IC >> 5;
    bool full = (p0 + 128 <= NP);

    const uint32_t* wr0 = wgt + (size_t)(oc0 + a_oc)*IC + a_kb;
    const float* br0 = inb + (size_t)b_kk*NP + p0 + b_pb;
    uint32_t adst0 = sbase + (a_oc*AW + a_kb)*4;
    uint32_t bdst0 = sbase + (2*ABUF + b_kk*BW + b_pb)*4;

    auto stage = [&](int buf, int it) {
        const uint32_t* wr = wr0 + it*32;
        uint32_t adst = adst0 + buf*(ABUF*4);
#pragma unroll
        for (int q = 0; q < 4; q++)
            cp16(adst + q*16, wr + q*4);
        const float* brow = br0 + (size_t)it*32*NP;
        uint32_t bdst = bdst0 + buf*(BBUF*4);
        if (full) {
#pragma unroll
            for (int q = 0; q < 4; q++)
                cp16(bdst + q*16, brow + q*4);
        } else {
            int pg = p0 + b_pb;
#pragma unroll
            for (int q = 0; q < 4; q++) {
                int rem = (NP - (pg + q*4)) * 4;
                int nb = rem >= 16 ? 16 : (rem > 0 ? rem : 0);
                const float* src = brow + q*4;
                if (nb == 0) src = inb;
                cp16z(bdst + q*16, src, nb);
            }
        }
    };

    stage(0, 0);
    asm volatile("cp.async.commit_group;");

    for (int it = 0; it < NIT; it++) {
        int buf = it & 1;
        if (it + 1 < NIT) {
            stage(buf ^ 1, it + 1);
            asm volatile("cp.async.commit_group;");
            asm volatile("cp.async.wait_group 1;");
        } else {
            asm volatile("cp.async.wait_group 0;");
        }
        __syncthreads();
        const uint32_t* Ab = Af + buf*ABUF;
        const uint32_t* Bb = Bf + buf*BBUF;
#pragma unroll
        for (int ks = 0; ks < 32; ks += 8) {
            uint32_t af[4][4];
#pragma unroll
            for (int mt = 0; mt < 4; mt++) {
                int oc = wm*64 + mt*16 + g;
                af[mt][0] = Ab[(oc  )*AW + ks + tig];
                af[mt][1] = Ab[(oc+8)*AW + ks + tig];
                af[mt][2] = Ab[(oc  )*AW + ks + tig + 4];
                af[mt][3] = Ab[(oc+8)*AW + ks + tig + 4];
            }
            uint32_t bf[4][2];
#pragma unroll
            for (int nt = 0; nt < 4; nt++) {
                int p = wn*32 + nt*8 + g;
                bf[nt][0] = Bb[(ks+tig  )*BW + p];
                bf[nt][1] = Bb[(ks+tig+4)*BW + p];
            }
#pragma unroll
            for (int mt = 0; mt < 4; mt++)
#pragma unroll
                for (int nt = 0; nt < 4; nt++)
                    mma_tf32(acc[mt][nt], af[mt][0], af[mt][1], af[mt][2], af[mt][3],
                             bf[nt][0], bf[nt][1]);
        }
        __syncthreads();
    }
    float* ob = out + (size_t)b * out_cstride * NP + (size_t)out_coff * NP;
#pragma unroll
    for (int mt = 0; mt < 4; mt++) {
        int r0 = oc0 + wm*64 + mt*16 + g;
        int r1 = r0 + 8;
        float bv0 = __ldg(bias + r0);
        float bv1 = __ldg(bias + r1);
        float* row0 = ob + (size_t)r0 * NP;
        float* row1 = ob + (size_t)r1 * NP;
#pragma unroll
        for (int nt = 0; nt < 4; nt++) {
            int c = p0 + wn*32 + nt*8 + tig*2;
            float4 a = acc[mt][nt];
            if (c + 1 < NP) {
                float2 v0; v0.x = a.x + bv0; v0.y = a.y + bv0;
                float2 v1; v1.x = a.z + bv1; v1.y = a.w + bv1;
                *(float2*)(row0 + c) = v0;
                *(float2*)(row1 + c) = v1;
            } else if (c < NP) {
                row0[c] = a.x + bv0;
                row1[c] = a.z + bv1;
            }
        }
    }
}

// ---------------- low-frequency global attention: flash tf32 MMA ----------------
#define LSM_WORDS 50432
__global__ __launch_bounds__(256) void lattn_mma_k(
    const float* __restrict__ q, const uint32_t* __restrict__ kvt,
    float* __restrict__ o) {
    extern __shared__ uint32_t Su[];
    uint32_t* Ps = Su;
    uint32_t* Ks = Su + 8704;
    uint32_t* Vs = Su + 27392;
    int b = blockIdx.z, h = blockIdx.y;
    int p0 = blockIdx.x * 128;
    int tid = threadIdx.x;
    int lane = tid & 31, w = tid >> 5;
    int g = lane >> 2, tig = lane & 3;
    const float* qb  = q + ((size_t)b*128 + h*32)*NP_FULL;
    const uint32_t* kvb = kvt + (size_t)(b*4 + h)*KVT_WORDS;
    uint32_t sbase = (uint32_t)__cvta_generic_to_shared(Su);

    for (int i = tid*4; i < KVT_WORDS; i += 1024)
        cp16(sbase + (8704 + i)*4, kvb + i);
    asm volatile("cp.async.commit_group;");

    for (int i = tid; i < 128*32; i += 256) {
        int d = i >> 7, pix = i & 127;
        Ps[pix*36 + d] = f2tf32(qb[(size_t)d*NP_FULL + p0 + pix] * SCALE);
    }
    asm volatile("cp.async.wait_group 0;");
    __syncthreads();

    int r0 = w*16 + g;
    uint32_t aq[4][4];
#pragma unroll
    for (int kt = 0; kt < 4; kt++) {
        aq[kt][0] = Ps[(r0  )*36 + kt*8 + tig];
        aq[kt][1] = Ps[(r0+8)*36 + kt*8 + tig];
        aq[kt][2] = Ps[(r0  )*36 + kt*8 + tig + 4];
        aq[kt][3] = Ps[(r0+8)*36 + kt*8 + tig + 4];
    }
    __syncwarp();

    float4 oacc[4];
#pragma unroll
    for (int dt = 0; dt < 4; dt++) oacc[dt] = make_float4(0.f,0.f,0.f,0.f);
    float m0 = -1e30f, m1 = -1e30f, l0 = 0.f, l1 = 0.f;

    for (int c = 0; c < 9; c++) {
        int kb = c*64;
        float4 s[8];
#pragma unroll
        for (int nt = 0; nt < 8; nt++) s[nt] = make_float4(0.f,0.f,0.f,0.f);
#pragma unroll
        for (int kt = 0; kt < 4; kt++) {
#pragma unroll
            for (int nt = 0; nt < 8; nt++) {
                uint32_t b0 = Ks[(kt*8+tig  )*584 + kb + nt*8 + g];
                uint32_t b1 = Ks[(kt*8+tig+4)*584 + kb + nt*8 + g];
                mma_tf32(s[nt], aq[kt][0], aq[kt][1], aq[kt][2], aq[kt][3], b0, b1);
            }
        }
        float mx0 = -1e30f, mx1 = -1e30f;
#pragma unroll
        for (int nt = 0; nt < 8; nt++) {
            mx0 = fmaxf(mx0, fmaxf(s[nt].x, s[nt].y));
            mx1 = fmaxf(mx1, fmaxf(s[nt].z, s[nt].w));
        }
        mx0 = fmaxf(mx0, __shfl_xor_sync(0xffffffffu, mx0, 1));
        mx0 = fmaxf(mx0, __shfl_xor_sync(0xffffffffu, mx0, 2));
        mx1 = fmaxf(mx1, __shfl_xor_sync(0xffffffffu, mx1, 1));
        mx1 = fmaxf(mx1, __shfl_xor_sync(0xffffffffu, mx1, 2));
        float nm0 = fmaxf(m0, mx0), nm1 = fmaxf(m1, mx1);
        float al0 = __expf(m0 - nm0), al1 = __expf(m1 - nm1);
        m0 = nm0; m1 = nm1;
        float sum0 = 0.f, sum1 = 0.f;
#pragma unroll
        for (int nt = 0; nt < 8; nt++) {
            s[nt].x = __expf(s[nt].x - m0); sum0 += s[nt].x;
            s[nt].y = __expf(s[nt].y - m0); sum0 += s[nt].y;
            s[nt].z = __expf(s[nt].z - m1); sum1 += s[nt].z;
            s[nt].w = __expf(s[nt].w - m1); sum1 += s[nt].w;
        }
        l0 = l0*al0 + sum0;
        l1 = l1*al1 + sum1;
#pragma unroll
        for (int dt = 0; dt < 4; dt++) {
            oacc[dt].x *= al0; oacc[dt].y *= al0;
            oacc[dt].z *= al1; oacc[dt].w *= al1;
        }
        __syncwarp();
#pragma unroll
        for (int nt = 0; nt < 8; nt++) {
            uint2 u0; u0.x = f2tf32(s[nt].x); u0.y = f2tf32(s[nt].y);
            uint2 u1; u1.x = f2tf32(s[nt].z); u1.y = f2tf32(s[nt].w);
            *(uint2*)&Ps[(r0  )*68 + nt*8 + 2*tig] = u0;
            *(uint2*)&Ps[(r0+8)*68 + nt*8 + 2*tig] = u1;
        }
        __syncwarp();
#pragma unroll
        for (int kt2 = 0; kt2 < 8; kt2++) {
            uint32_t a0 = Ps[(r0  )*68 + kt2*8 + tig];
            uint32_t a1 = Ps[(r0+8)*68 + kt2*8 + tig];
            uint32_t a2 = Ps[(r0  )*68 + kt2*8 + tig + 4];
            uint32_t a3 = Ps[(r0+8)*68 + kt2*8 + tig + 4];
#pragma unroll
            for (int dt = 0; dt < 4; dt++) {
                uint32_t b0 = Vs[(kb + kt2*8 + tig  )*40 + dt*8 + g];
                uint32_t b1 = Vs[(kb + kt2*8 + tig+4)*40 + dt*8 + g];
                mma_tf32(oacc[dt], a0, a1, a2, a3, b0, b1);
            }
        }
    }
    l0 += __shfl_xor_sync(0xffffffffu, l0, 1);
    l0 += __shfl_xor_sync(0xffffffffu, l0, 2);
    l1 += __shfl_xor_sync(0xffffffffu, l1, 1);
    l1 += __shfl_xor_sync(0xffffffffu, l1, 2);
    float inv0 = 1.f / l0, inv1 = 1.f / l1;
    float* ob = o + ((size_t)b*128 + h*32)*NP_FULL + p0;
#pragma unroll
    for (int dt = 0; dt < 4; dt++) {
        int d0 = dt*8 + 2*tig;
        ob[(size_t)(d0  )*NP_FULL + r0    ] = oacc[dt].x * inv0;
        ob[(size_t)(d0+1)*NP_FULL + r0    ] = oacc[dt].y * inv0;
        ob[(size_t)(d0  )*NP_FULL + r0 + 8] = oacc[dt].z * inv1;
        ob[(size_t)(d0+1)*NP_FULL + r0 + 8] = oacc[dt].w * inv1;
    }
}

// ---------------- high-frequency windowed attention: tf32 MMA ----------------
#define HSM_WORDS (24*576)
__global__ __launch_bounds__(256) void hattn_mma_k(
    const float* __restrict__ qkv, float* __restrict__ ho) {
    extern __shared__ uint32_t Hsm[];
    int b = blockIdx.y;
    int g0 = blockIdx.x * 2;
    const float* qb = qkv + (size_t)b*384*NP_FULL;
    int tid = threadIdx.x;
    for (int i = tid; i < 384*32; i += 256) {
        int c = i >> 5;
        int wt = i & 31;
        int win = wt >> 4, t = wt & 15;
        int which = c >> 7;
        int n = (c >> 5) & 3;
        int d = c & 31;
        int gg = g0 + win; int gy = gg / HGD, gx = gg - gy*HGD;
        int pp = (gy*4 + (t >> 2))*WW_ + gx*4 + (t & 3);
        float v = qb[(size_t)c*NP_FULL + pp];
        if (which == 0) v *= SCALE;
        Hsm[((win*4 + n)*3 + which)*576 + t*36 + d] = f2tf32(v);
    }
    __syncthreads();
    int lane = tid & 31, w = tid >> 5;
    int win = w >> 2, n = w & 3;
    int g = lane >> 2, tig = lane & 3;
    uint32_t* QB = Hsm + ((win*4 + n)*3 + 0)*576;
    uint32_t* KB = Hsm + ((win*4 + n)*3 + 1)*576;
    uint32_t* VB = Hsm + ((win*4 + n)*3 + 2)*576;
    float4 s[2];
    s[0] = make_float4(0.f,0.f,0.f,0.f);
    s[1] = make_float4(0.f,0.f,0.f,0.f);
#pragma unroll
    for (int ks = 0; ks < 32; ks += 8) {
        uint32_t a0 = QB[(g  )*36 + ks + tig];
        uint32_t a1 = QB[(g+8)*36 + ks + tig];
        uint32_t a2 = QB[(g  )*36 + ks + tig + 4];
        uint32_t a3 = QB[(g+8)*36 + ks + tig + 4];
#pragma unroll
        for (int nt = 0; nt < 2; nt++) {
            uint32_t b0 = KB[(nt*8+g)*36 + ks + tig];
            uint32_t b1 = KB[(nt*8+g)*36 + ks + tig + 4];
            mma_tf32(s[nt], a0, a1, a2, a3, b0, b1);
        }
    }
    float mx0 = fmaxf(fmaxf(s[0].x, s[0].y), fmaxf(s[1].x, s[1].y));
    float mx1 = fmaxf(fmaxf(s[0].z, s[0].w), fmaxf(s[1].z, s[1].w));
    mx0 = fmaxf(mx0, __shfl_xor_sync(0xffffffffu, mx0, 1));
    mx0 = fmaxf(mx0, __shfl_xor_sync(0xffffffffu, mx0, 2));
    mx1 = fmaxf(mx1, __shfl_xor_sync(0xffffffffu, mx1, 1));
    mx1 = fmaxf(mx1, __shfl_xor_sync(0xffffffffu, mx1, 2));
    float l0 = 0.f, l1 = 0.f;
#pragma unroll
    for (int nt = 0; nt < 2; nt++) {
        s[nt].x = __expf(s[nt].x - mx0); l0 += s[nt].x;
        s[nt].y = __expf(s[nt].y - mx0); l0 += s[nt].y;
        s[nt].z = __expf(s[nt].z - mx1); l1 += s[nt].z;
        s[nt].w = __expf(s[nt].w - mx1); l1 += s[nt].w;
    }
    l0 += __shfl_xor_sync(0xffffffffu, l0, 1);
    l0 += __shfl_xor_sync(0xffffffffu, l0, 2);
    l1 += __shfl_xor_sync(0xffffffffu, l1, 1);
    l1 += __shfl_xor_sync(0xffffffffu, l1, 2);
    float inv0 = 1.f / l0, inv1 = 1.f / l1;
    __syncwarp();
#pragma unroll
    for (int nt = 0; nt < 2; nt++) {
        QB[(g  )*36 + nt*8 + 2*tig    ] = f2tf32(s[nt].x * inv0);
        QB[(g  )*36 + nt*8 + 2*tig + 1] = f2tf32(s[nt].y * inv0);
        QB[(g+8)*36 + nt*8 + 2*tig    ] = f2tf32(s[nt].z * inv1);
        QB[(g+8)*36 + nt*8 + 2*tig + 1] = f2tf32(s[nt].w * inv1);
    }
    __syncwarp();
    float4 o[4];
#pragma unroll
    for (int dt = 0; dt < 4; dt++) o[dt] = make_float4(0.f,0.f,0.f,0.f);
#pragma unroll
    for (int ks = 0; ks < 16; ks += 8) {
        uint32_t a0 = QB[(g  )*36 + ks + tig];
        uint32_t a1 = QB[(g+8)*36 + ks + tig];
        uint32_t a2 = QB[(g  )*36 + ks + tig + 4];
        uint32_t a3 = QB[(g+8)*36 + ks + tig + 4];
#pragma unroll
        for (int dt = 0; dt < 4; dt++) {
            uint32_t b0 = VB[(ks+tig  )*36 + dt*8 + g];
            uint32_t b1 = VB[(ks+tig+4)*36 + dt*8 + g];
            mma_tf32(o[dt], a0, a1, a2, a3, b0, b1);
        }
    }
    int gw = g0 + win; int gy = gw / HGD, gx = gw - gy*HGD;
    int pbase = gy*4*WW_ + gx*4;
    int pp0 = pbase + ((g  ) >> 2)*WW_ + ((g  ) & 3);
    int pp1 = pbase + ((g+8) >> 2)*WW_ + ((g+8) & 3);
    float* ob = ho + (size_t)b*128*NP_FULL;
#pragma unroll
    for (int dt = 0; dt < 4; dt++) {
        int d = n*32 + dt*8 + 2*tig;
        ob[(size_t)(d  )*NP_FULL + pp0] = o[dt].x;
        ob[(size_t)(d+1)*NP_FULL + pp0] = o[dt].y;
        ob[(size_t)(d  )*NP_FULL + pp1] = o[dt].z;
        ob[(size_t)(d+1)*NP_FULL + pp1] = o[dt].w;
    }
}

// ---------------- launch ----------------
extern "C" void kernel_launch(void* const* d_in, const int* in_sizes, int n_in,
                              void* d_out, int out_size) {
    const float* x          = (const float*)d_in[0];
    const float* restore_w  = (const float*)d_in[1];
    const float* restore_b  = (const float*)d_in[2];
    const float* lq_dw_w    = (const float*)d_in[3];
    const float* lq_dw_b    = (const float*)d_in[4];
    const float* lq_pw_w    = (const float*)d_in[5];
    const float* lq_pw_b    = (const float*)d_in[6];
    const float* lkv_dw_w   = (const float*)d_in[7];
    const float* lkv_dw_b   = (const float*)d_in[8];
    const float* lkv_pw_w   = (const float*)d_in[9];
    const float* lkv_pw_b   = (const float*)d_in[10];
    const float* lproj_dw_w = (const float*)d_in[11];
    const float* lproj_dw_b = (const float*)d_in[12];
    const float* lproj_pw_w = (const float*)d_in[13];
    const float* lproj_pw_b = (const float*)d_in[14];
    const float* hqkv_dw_w  = (const float*)d_in[15];
    const float* hqkv_dw_b  = (const float*)d_in[16];
    const float* hqkv_pw_w  = (const float*)d_in[17];
    const float* hqkv_pw_b  = (const float*)d_in[18];
    const float* hproj_dw_w = (const float*)d_in[19];
    const float* hproj_dw_b = (const float*)d_in[20];
    const float* hproj_pw_w = (const float*)d_in[21];
    const float* hproj_pw_b = (const float*)d_in[22];
    float* out = (float*)d_out;

    float *low, *high, *dwA, *dwB, *lkvdw, *lq, *lkv, *lattn, *qkvb, *ho;
    uint32_t *kvt, *wt;
    cudaGetSymbolAddress((void**)&low,   g_low);
    cudaGetSymbolAddress((void**)&high,  g_high);
    cudaGetSymbolAddress((void**)&dwA,   g_dw);
    cudaGetSymbolAddress((void**)&dwB,   g_dw2);
    cudaGetSymbolAddress((void**)&lkvdw, g_lkvdw);
    cudaGetSymbolAddress((void**)&wt,    g_wt);
    cudaGetSymbolAddress((void**)&lq,    g_lq);
    cudaGetSymbolAddress((void**)&lkv,   g_lkv);
    cudaGetSymbolAddress((void**)&kvt,   g_kvt);
    cudaGetSymbolAddress((void**)&lattn, g_lattn);
    cudaGetSymbolAddress((void**)&qkvb,  g_qkv);
    cudaGetSymbolAddress((void**)&ho,    g_ho);

    static cudaStream_t s2 = nullptr, s3 = nullptr;
    static cudaEvent_t evFork = nullptr, evJoin = nullptr, evLkv = nullptr;
    if (!s2) {
        cudaStreamCreateWithFlags(&s2, cudaStreamNonBlocking);
        cudaStreamCreateWithFlags(&s3, cudaStreamNonBlocking);
        cudaEventCreateWithFlags(&evFork, cudaEventDisableTiming);
        cudaEventCreateWithFlags(&evJoin, cudaEventDisableTiming);
        cudaEventCreateWithFlags(&evLkv, cudaEventDisableTiming);
        cudaFuncSetAttribute(pw_mma_k, cudaFuncAttributeMaxDynamicSharedMemorySize, PW_SMEM);
        cudaFuncSetAttribute(lattn_mma_k, cudaFuncAttributeMaxDynamicSharedMemorySize, LSM_WORDS*4);
        cudaFuncSetAttribute(hattn_mma_k, cudaFuncAttributeMaxDynamicSharedMemorySize, HSM_WORDS*4);
    }

    // ---- weight conversion (overlapped at stream heads) ----
    wcvt_k<<<(98304+255)/256, 256, 0, s2>>>(hqkv_pw_w,  wt + WT_HQKV,  98304);
    wcvt_k<<<(16384+255)/256, 256, 0, s2>>>(hproj_pw_w, wt + WT_HPROJ, 16384);
    wcvt_k<<<(65536+255)/256, 256, 0, s3>>>(lkv_pw_w,   wt + WT_LKV,   65536);

    // ---- stream 0: pool (feeds all chains) + low-chain weight cvt ----
    {
        int total = BB*CC*GP;
        pool_k<<<(total + 255)/256, 256, 0>>>(x, low);
    }
    cudaEventRecord(evFork, 0);
    cudaStreamWaitEvent(s2, evFork, 0);
    cudaStreamWaitEvent(s3, evFork, 0);
    wcvt_k<<<(32768+255)/256, 256, 0>>>(lq_pw_w,    wt + WT_LQ,    32768);
    wcvt_k<<<(16384+255)/256, 256, 0>>>(lproj_pw_w, wt + WT_LPROJ, 16384);

    // ======== LKV mini-chain on s3 ========
    {
        int total16 = BB*CC*GP/16;
        dw_k<<<(total16 + 255)/256, 256, 0, s3>>>(low, lkv_dw_w, lkv_dw_b, lkvdw, CC, HGD, HGD, total16);
    }
    pw_mma_k<<<dim3((GP + 127)/128, 2, BB), 256, PW_SMEM, s3>>>(lkvdw, wt + WT_LKV, lkv_pw_b, lkv, 256, GP, 256, 0);
    {
        int total = 32*KVT_WORDS;
        kvprep_k<<<(total + 255)/256, 256, 0, s3>>>(lkv, kvt);
    }
    cudaEventRecord(evLkv, s3);

    // ======== HIGH chain on s2 ========
    high_k<<<dim3(NP_FULL/256, BB, 4), 256, 0, s2>>>(x, low, restore_w, restore_b, high);
    {
        int total16 = BB*CC*NP_FULL/16;
        dw_k<<<(total16 + 255)/256, 256, 0, s2>>>(high, hqkv_dw_w, hqkv_dw_b, dwB, CC, HH_, WW_, total16);
    }
    pw_mma_k<<<dim3(NP_FULL/128, 3, BB), 256, PW_SMEM, s2>>>(dwB, wt + WT_HQKV, hqkv_pw_b, qkvb, 256, NP_FULL, 384, 0);
    hattn_mma_k<<<dim3(GP/2, BB), 256, HSM_WORDS*4, s2>>>(qkvb, ho);
    {
        int total16 = BB*128*NP_FULL/16;
        dw_k<<<(total16 + 255)/256, 256, 0, s2>>>(ho, hproj_dw_w, hproj_dw_b, dwB, 128, HH_, WW_, total16);
    }
    pw_mma_k<<<dim3(NP_FULL/128, 1, BB), 256, PW_SMEM, s2>>>(dwB, wt + WT_HPROJ, hproj_pw_b, out, 128, NP_FULL, 256, 128);
    cudaEventRecord(evJoin, s2);

    // ======== LOW chain on stream 0 ========
    {
        int total16 = BB*CC*NP_FULL/16;
        dw_k<<<(total16 + 255)/256, 256, 0>>>(x, lq_dw_w, lq_dw_b, dwA, CC, HH_, WW_, total16);
    }
    pw_mma_k<<<dim3(NP_FULL/128, 1, BB), 256, PW_SMEM>>>(dwA, wt + WT_LQ, lq_pw_b, lq, 256, NP_FULL, 128, 0);
    cudaStreamWaitEvent(0, evLkv, 0);
    lattn_mma_k<<<dim3(NP_FULL/128, 4, BB), 256, LSM_WORDS*4>>>(lq, kvt, lattn);
    {
        int total16 = BB*128*NP_FULL/16;
        dw_k<<<(total16 + 255)/256, 256, 0>>>(lattn, lproj_dw_w, lproj_dw_b, dwA, 128, HH_, WW_, total16);
    }
    pw_mma_k<<<dim3(NP_FULL/128, 1, BB), 256, PW_SMEM>>>(dwA, wt + WT_LPROJ, lproj_pw_b, out, 128, NP_FULL, 256, 0);

    // ---- join ----
    cudaStreamWaitEvent(0, evJoin, 0);
}